// round 1
// baseline (speedup 1.0000x reference)
#include <cuda_runtime.h>
#include <math.h>

#define Bb 4
#define Tt 2048
#define Cc 1024
#define Hh 16
#define Dd 64
#define Mrows (Bb*Tt)

// Scratch (alloc-free rule: __device__ globals)
__device__ float g_q[(size_t)Bb*Hh*Tt*Dd];
__device__ float g_k[(size_t)Bb*Hh*Tt*Dd];
__device__ float g_v[(size_t)Bb*Hh*Tt*Dd];
__device__ float g_y[(size_t)Bb*Tt*Cc];

// ---------------------------------------------------------------------------
// Tiled fp32 GEMM: Out[M,N] = A[M,1024] * W[1024,N] + bias
// 64x64 block tile, 256 threads, 4x4 micro-tile, BK=16.
// SCATTER=true: epilogue scatters qkv columns into g_q/g_k/g_v [B,H,T,D].
// SCATTER=false: A is g_y, direct write to Out.
// ---------------------------------------------------------------------------
template<int N, bool SCATTER>
__global__ __launch_bounds__(256, 1) void gemm_kernel(
    const float* __restrict__ A, const float* __restrict__ W,
    const float* __restrict__ bias, float* __restrict__ Out)
{
    __shared__ float As[16][65];   // [k][m] transposed
    __shared__ float Bs[16][68];   // [k][n]

    const int K = Cc;
    const int tid = threadIdx.x;
    const int tx = tid & 15, ty = tid >> 4;
    const int rowBase = blockIdx.y * 64;
    const int colBase = blockIdx.x * 64;

    const int ar = tid >> 2;         // 0..63 (m within tile)
    const int ac = (tid & 3) << 2;   // 0,4,8,12 (k within tile)
    const int bc = tid >> 4;         // 0..15 (k within tile)
    const int br = (tid & 15) << 2;  // 0..60 (n within tile)

    const float* Abase = SCATTER ? A : g_y;

    float acc[4][4];
#pragma unroll
    for (int i = 0; i < 4; i++)
#pragma unroll
        for (int j = 0; j < 4; j++) acc[i][j] = 0.0f;

    const float* Aptr = Abase + (size_t)(rowBase + ar) * K + ac;
    const float* Wptr = W + (size_t)bc * N + colBase + br;

    for (int k0 = 0; k0 < K; k0 += 16) {
        float4 a4 = *(const float4*)(Aptr + k0);
        float4 b4 = *(const float4*)(Wptr + (size_t)k0 * N);
        __syncthreads();
        As[ac + 0][ar] = a4.x;
        As[ac + 1][ar] = a4.y;
        As[ac + 2][ar] = a4.z;
        As[ac + 3][ar] = a4.w;
        *(float4*)&Bs[bc][br] = b4;
        __syncthreads();
#pragma unroll
        for (int kk = 0; kk < 16; kk++) {
            float a0 = As[kk][ty * 4 + 0];
            float a1 = As[kk][ty * 4 + 1];
            float a2 = As[kk][ty * 4 + 2];
            float a3 = As[kk][ty * 4 + 3];
            float4 b = *(const float4*)&Bs[kk][tx * 4];
            acc[0][0] += a0 * b.x; acc[0][1] += a0 * b.y; acc[0][2] += a0 * b.z; acc[0][3] += a0 * b.w;
            acc[1][0] += a1 * b.x; acc[1][1] += a1 * b.y; acc[1][2] += a1 * b.z; acc[1][3] += a1 * b.w;
            acc[2][0] += a2 * b.x; acc[2][1] += a2 * b.y; acc[2][2] += a2 * b.z; acc[2][3] += a2 * b.w;
            acc[3][0] += a3 * b.x; acc[3][1] += a3 * b.y; acc[3][2] += a3 * b.z; acc[3][3] += a3 * b.w;
        }
    }

    float bj[4];
#pragma unroll
    for (int j = 0; j < 4; j++) bj[j] = bias[colBase + tx * 4 + j];

    if (SCATTER) {
        // qkv tile: 64 columns fall inside exactly one of q/k/v and one head
        const int n0 = colBase;
        const int which = n0 / Cc;
        const int h = (n0 % Cc) / Dd;
        float* outp = (which == 0) ? g_q : ((which == 1) ? g_k : g_v);
#pragma unroll
        for (int i = 0; i < 4; i++) {
            int m = rowBase + ty * 4 + i;
            int b = m / Tt, t = m % Tt;
            float4 v;
            v.x = acc[i][0] + bj[0];
            v.y = acc[i][1] + bj[1];
            v.z = acc[i][2] + bj[2];
            v.w = acc[i][3] + bj[3];
            *(float4*)&outp[(((size_t)(b * Hh + h)) * Tt + t) * Dd + tx * 4] = v;
        }
    } else {
#pragma unroll
        for (int i = 0; i < 4; i++) {
            int m = rowBase + ty * 4 + i;
            float4 v;
            v.x = acc[i][0] + bj[0];
            v.y = acc[i][1] + bj[1];
            v.z = acc[i][2] + bj[2];
            v.w = acc[i][3] + bj[3];
            *(float4*)&Out[(size_t)m * N + colBase + tx * 4] = v;
        }
    }
}

// ---------------------------------------------------------------------------
// Flash attention (causal), fp32. One block = one (b*h, 64-row q tile).
// 256 threads, 16x16 grid, 4x4 micro for both S (q x k) and O (q x d).
// Online softmax; P reuses K's smem region.
// ---------------------------------------------------------------------------
#define SM_Q 0
#define SM_KP (64 * 68)
#define SM_V (2 * 64 * 68)
#define ATTN_SMEM (3 * 64 * 68 * 4)

__device__ __forceinline__ float rmax16(float v) {
#pragma unroll
    for (int off = 8; off; off >>= 1)
        v = fmaxf(v, __shfl_xor_sync(0xffffffffu, v, off));
    return v;
}
__device__ __forceinline__ float rsum16(float v) {
#pragma unroll
    for (int off = 8; off; off >>= 1)
        v += __shfl_xor_sync(0xffffffffu, v, off);
    return v;
}

__global__ __launch_bounds__(256, 1) void attn_kernel()
{
    extern __shared__ float sm[];
    float* Qs = sm + SM_Q;    // [64][68]  Qs[q][d]
    float* KPs = sm + SM_KP;  // [64][68]  first K^T: [d][k]; then P: [q][k]
    float* Vs = sm + SM_V;    // [64][68]  Vs[k][d]

    const int tid = threadIdx.x;
    const int tx = tid & 15, ty = tid >> 4;
    const int bh = blockIdx.y;
    const int qt = gridDim.x - 1 - blockIdx.x;  // heavy tiles first

    const float* Qg = g_q + (size_t)bh * Tt * Dd;
    const float* Kg = g_k + (size_t)bh * Tt * Dd;
    const float* Vg = g_v + (size_t)bh * Tt * Dd;

    const int lr = tid >> 2;         // 0..63 row
    const int lc = (tid & 3) << 4;   // 0,16,32,48 col base

    // Load Q tile [64][64] -> Qs
    {
        const float* src = Qg + ((size_t)qt * 64 + lr) * Dd + lc;
#pragma unroll
        for (int q = 0; q < 4; q++) {
            float4 v = *(const float4*)(src + q * 4);
            *(float4*)&Qs[lr * 68 + lc + q * 4] = v;
        }
    }

    float m_r[4], l_r[4], acc[4][4];
#pragma unroll
    for (int i = 0; i < 4; i++) {
        m_r[i] = -1e30f;
        l_r[i] = 0.0f;
#pragma unroll
        for (int j = 0; j < 4; j++) acc[i][j] = 0.0f;
    }

    for (int kt = 0; kt <= qt; kt++) {
        __syncthreads();  // previous iter done with KPs/Vs
        // Load K (transposed) and V tiles
        {
            const float* ks = Kg + ((size_t)kt * 64 + lr) * Dd + lc;
            const float* vs = Vg + ((size_t)kt * 64 + lr) * Dd + lc;
#pragma unroll
            for (int q = 0; q < 4; q++) {
                int d0 = lc + q * 4;
                float4 kv = *(const float4*)(ks + q * 4);
                KPs[(d0 + 0) * 68 + lr] = kv.x;
                KPs[(d0 + 1) * 68 + lr] = kv.y;
                KPs[(d0 + 2) * 68 + lr] = kv.z;
                KPs[(d0 + 3) * 68 + lr] = kv.w;
                float4 vv = *(const float4*)(vs + q * 4);
                *(float4*)&Vs[lr * 68 + d0] = vv;
            }
        }
        __syncthreads();

        // S = Q * K^T  (4x4 micro per thread)
        float s[4][4];
#pragma unroll
        for (int i = 0; i < 4; i++)
#pragma unroll
            for (int j = 0; j < 4; j++) s[i][j] = 0.0f;
#pragma unroll 8
        for (int kd = 0; kd < 64; kd++) {
            float a0 = Qs[(ty * 4 + 0) * 68 + kd];
            float a1 = Qs[(ty * 4 + 1) * 68 + kd];
            float a2 = Qs[(ty * 4 + 2) * 68 + kd];
            float a3 = Qs[(ty * 4 + 3) * 68 + kd];
            float4 b = *(const float4*)&KPs[kd * 68 + tx * 4];
            s[0][0] += a0 * b.x; s[0][1] += a0 * b.y; s[0][2] += a0 * b.z; s[0][3] += a0 * b.w;
            s[1][0] += a1 * b.x; s[1][1] += a1 * b.y; s[1][2] += a1 * b.z; s[1][3] += a1 * b.w;
            s[2][0] += a2 * b.x; s[2][1] += a2 * b.y; s[2][2] += a2 * b.z; s[2][3] += a2 * b.w;
            s[3][0] += a3 * b.x; s[3][1] += a3 * b.y; s[3][2] += a3 * b.z; s[3][3] += a3 * b.w;
        }

        // scale + causal mask (only the diagonal tile needs masking)
        const float scale = 0.125f;  // 1/sqrt(64)
        if (kt == qt) {
#pragma unroll
            for (int i = 0; i < 4; i++)
#pragma unroll
                for (int j = 0; j < 4; j++)
                    s[i][j] = (tx * 4 + j > ty * 4 + i) ? -1e30f : s[i][j] * scale;
        } else {
#pragma unroll
            for (int i = 0; i < 4; i++)
#pragma unroll
                for (int j = 0; j < 4; j++) s[i][j] *= scale;
        }

        // online softmax
        float mnew[4], corr[4], rs[4];
#pragma unroll
        for (int i = 0; i < 4; i++) {
            float m = fmaxf(fmaxf(s[i][0], s[i][1]), fmaxf(s[i][2], s[i][3]));
            m = rmax16(m);
            mnew[i] = fmaxf(m_r[i], m);
            corr[i] = __expf(m_r[i] - mnew[i]);
            float sum = 0.0f;
#pragma unroll
            for (int j = 0; j < 4; j++) {
                s[i][j] = __expf(s[i][j] - mnew[i]);
                sum += s[i][j];
            }
            rs[i] = rsum16(sum);
            l_r[i] = l_r[i] * corr[i] + rs[i];
            m_r[i] = mnew[i];
#pragma unroll
            for (int j = 0; j < 4; j++) acc[i][j] *= corr[i];
        }

        __syncthreads();  // all threads done reading KPs as K
        // store P (reuse KPs region): P[q][k]
#pragma unroll
        for (int i = 0; i < 4; i++) {
            float4 p;
            p.x = s[i][0]; p.y = s[i][1]; p.z = s[i][2]; p.w = s[i][3];
            *(float4*)&KPs[(ty * 4 + i) * 68 + tx * 4] = p;
        }
        __syncthreads();

        // O += P * V
#pragma unroll 8
        for (int kc = 0; kc < 64; kc++) {
            float p0 = KPs[(ty * 4 + 0) * 68 + kc];
            float p1 = KPs[(ty * 4 + 1) * 68 + kc];
            float p2 = KPs[(ty * 4 + 2) * 68 + kc];
            float p3 = KPs[(ty * 4 + 3) * 68 + kc];
            float4 v = *(const float4*)&Vs[kc * 68 + tx * 4];
            acc[0][0] += p0 * v.x; acc[0][1] += p0 * v.y; acc[0][2] += p0 * v.z; acc[0][3] += p0 * v.w;
            acc[1][0] += p1 * v.x; acc[1][1] += p1 * v.y; acc[1][2] += p1 * v.z; acc[1][3] += p1 * v.w;
            acc[2][0] += p2 * v.x; acc[2][1] += p2 * v.y; acc[2][2] += p2 * v.z; acc[2][3] += p2 * v.w;
            acc[3][0] += p3 * v.x; acc[3][1] += p3 * v.y; acc[3][2] += p3 * v.z; acc[3][3] += p3 * v.w;
        }
    }

    // normalize + write y in [B,T,C] layout
    const int b = bh / Hh, h = bh % Hh;
#pragma unroll
    for (int i = 0; i < 4; i++) {
        float inv = 1.0f / l_r[i];
        int t = qt * 64 + ty * 4 + i;
        float4 o;
        o.x = acc[i][0] * inv;
        o.y = acc[i][1] * inv;
        o.z = acc[i][2] * inv;
        o.w = acc[i][3] * inv;
        *(float4*)&g_y[((size_t)b * Tt + t) * Cc + h * Dd + tx * 4] = o;
    }
}

// ---------------------------------------------------------------------------

extern "C" void kernel_launch(void* const* d_in, const int* in_sizes, int n_in,
                              void* d_out, int out_size)
{
    const float* x = (const float*)d_in[0];
    const float* w_qkv = (const float*)d_in[1];
    const float* b_qkv = (const float*)d_in[2];
    const float* w_proj = (const float*)d_in[3];
    const float* b_proj = (const float*)d_in[4];
    float* out = (float*)d_out;

    cudaFuncSetAttribute(attn_kernel, cudaFuncAttributeMaxDynamicSharedMemorySize, ATTN_SMEM);

    // QKV GEMM: [8192,1024] x [1024,3072] -> scatter to g_q/g_k/g_v
    gemm_kernel<3 * Cc, true><<<dim3(48, 128), 256>>>(x, w_qkv, b_qkv, nullptr);
    // Flash attention: g_q/g_k/g_v -> g_y
    attn_kernel<<<dim3(Tt / 64, Bb * Hh), 256, ATTN_SMEM>>>();
    // Proj GEMM: g_y [8192,1024] x [1024,1024] + bias -> out
    gemm_kernel<Cc, false><<<dim3(16, 128), 256>>>(nullptr, w_proj, b_proj, out);
}

// round 5
// speedup vs baseline: 1.4952x; 1.4952x over previous
#include <cuda_runtime.h>
#include <math.h>
#include <stdint.h>

#define Bb 4
#define Tt 2048
#define Cc 1024
#define Hh 16
#define Dd 64

// Scratch (alloc-free rule: __device__ globals)
__device__ float g_q[(size_t)Bb*Hh*Tt*Dd];
__device__ float g_k[(size_t)Bb*Hh*Tt*Dd];
__device__ float g_v[(size_t)Bb*Hh*Tt*Dd];
__device__ float g_y[(size_t)Bb*Tt*Cc];

__device__ __forceinline__ float totf32(float x) {
    uint32_t u;
    asm("cvt.rna.tf32.f32 %0, %1;" : "=r"(u) : "f"(x));
    return __uint_as_float(u);
}

__device__ __forceinline__ void mma_tf32(float4& c,
    uint32_t a0, uint32_t a1, uint32_t a2, uint32_t a3,
    uint32_t b0, uint32_t b1)
{
    asm volatile(
        "mma.sync.aligned.m16n8k8.row.col.f32.tf32.tf32.f32 "
        "{%0,%1,%2,%3}, {%4,%5,%6,%7}, {%8,%9}, {%0,%1,%2,%3};\n"
        : "+f"(c.x), "+f"(c.y), "+f"(c.z), "+f"(c.w)
        : "r"(a0), "r"(a1), "r"(a2), "r"(a3), "r"(b0), "r"(b1));
}

// ---------------------------------------------------------------------------
// TF32 tensor-core GEMM: Out[M,N] = A[M,1024] * W[1024,N] + bias
// 128x128 CTA tile, BK=32, 256 threads (8 warps, 2x4), warp tile 64x32.
// SCATTER=true: qkv epilogue scatters into g_q/g_k/g_v [B,H,T,D].
// ---------------------------------------------------------------------------
template<int N, bool SCATTER>
__global__ __launch_bounds__(256, 1) void gemm_tc(
    const float* __restrict__ A, const float* __restrict__ W,
    const float* __restrict__ bias, float* __restrict__ Out)
{
    const int K = Cc;
    __shared__ float As[32][136];  // [k][m], stride 136 -> conflict-free frags
    __shared__ float Bs[32][136];  // [k][n]

    const int tid = threadIdx.x;
    const int wid = tid >> 5, lane = tid & 31;
    const int warp_m = wid >> 2, warp_n = wid & 3;
    const int g = lane >> 2, r = lane & 3;

    const int mBlk = blockIdx.y * 128, nBlk = blockIdx.x * 128;

    const float* Abase = SCATTER ? A : g_y;

    // A staging: m = tid>>1 (0..127), k0 = (tid&1)*16, 4 float4 (16 k's)
    const int am = tid >> 1, ak = (tid & 1) * 16;
    const float* aptr = Abase + (size_t)(mBlk + am) * K + ak;
    // B staging: k = tid>>3 (0..31), n0 = (tid&7)*16, 4 float4 (16 n's)
    const int bk = tid >> 3, bn = (tid & 7) * 16;
    const float* wptr = W + (size_t)bk * N + nBlk + bn;

    float4 aReg[4], bReg[4];
#pragma unroll
    for (int i = 0; i < 4; i++) aReg[i] = *(const float4*)(aptr + i * 4);
#pragma unroll
    for (int i = 0; i < 4; i++) bReg[i] = *(const float4*)(wptr + i * 4);

    float4 acc[4][4];
#pragma unroll
    for (int i = 0; i < 4; i++)
#pragma unroll
        for (int j = 0; j < 4; j++) acc[i][j] = make_float4(0.f, 0.f, 0.f, 0.f);

    for (int kt = 0; kt < K / 32; kt++) {
        __syncthreads();
        // STS A transposed (with tf32 rounding)
#pragma unroll
        for (int i = 0; i < 4; i++) {
            As[ak + i * 4 + 0][am] = totf32(aReg[i].x);
            As[ak + i * 4 + 1][am] = totf32(aReg[i].y);
            As[ak + i * 4 + 2][am] = totf32(aReg[i].z);
            As[ak + i * 4 + 3][am] = totf32(aReg[i].w);
        }
        // STS B (with tf32 rounding)
#pragma unroll
        for (int i = 0; i < 4; i++) {
            float4 t;
            t.x = totf32(bReg[i].x); t.y = totf32(bReg[i].y);
            t.z = totf32(bReg[i].z); t.w = totf32(bReg[i].w);
            *(float4*)&Bs[bk][bn + i * 4] = t;
        }
        __syncthreads();

        // prefetch next k-chunk while computing
        if (kt + 1 < K / 32) {
            aptr += 32;
            wptr += (size_t)32 * N;
#pragma unroll
            for (int i = 0; i < 4; i++) aReg[i] = *(const float4*)(aptr + i * 4);
#pragma unroll
            for (int i = 0; i < 4; i++) bReg[i] = *(const float4*)(wptr + i * 4);
        }

#pragma unroll
        for (int kk = 0; kk < 4; kk++) {
            const int k = kk * 8;
            uint32_t af[4][4], bf[4][2];
#pragma unroll
            for (int mt = 0; mt < 4; mt++) {
                const int m0 = warp_m * 64 + mt * 16 + g;
                af[mt][0] = __float_as_uint(As[k + r][m0]);
                af[mt][1] = __float_as_uint(As[k + r][m0 + 8]);
                af[mt][2] = __float_as_uint(As[k + r + 4][m0]);
                af[mt][3] = __float_as_uint(As[k + r + 4][m0 + 8]);
            }
#pragma unroll
            for (int nt = 0; nt < 4; nt++) {
                const int n0 = warp_n * 32 + nt * 8 + g;
                bf[nt][0] = __float_as_uint(Bs[k + r][n0]);
                bf[nt][1] = __float_as_uint(Bs[k + r + 4][n0]);
            }
#pragma unroll
            for (int mt = 0; mt < 4; mt++)
#pragma unroll
                for (int nt = 0; nt < 4; nt++)
                    mma_tf32(acc[mt][nt],
                             af[mt][0], af[mt][1], af[mt][2], af[mt][3],
                             bf[nt][0], bf[nt][1]);
        }
    }

    // Epilogue. c0,c1 = (row g, cols 2r,2r+1); c2,c3 = (row g+8, same cols)
#pragma unroll
    for (int mt = 0; mt < 4; mt++) {
        const int mA = mBlk + warp_m * 64 + mt * 16 + g;
        const int mB = mA + 8;
#pragma unroll
        for (int nt = 0; nt < 4; nt++) {
            const int n = nBlk + warp_n * 32 + nt * 8 + 2 * r;
            const float b0 = bias[n], b1 = bias[n + 1];
            float2 v0 = make_float2(acc[mt][nt].x + b0, acc[mt][nt].y + b1);
            float2 v1 = make_float2(acc[mt][nt].z + b0, acc[mt][nt].w + b1);
            if (SCATTER) {
                const int which = n >> 10;
                const int h = (n & 1023) >> 6;
                const int d = n & 63;
                float* outp = (which == 0) ? g_q : ((which == 1) ? g_k : g_v);
                {
                    const int b_ = mA >> 11, t_ = mA & 2047;
                    *(float2*)&outp[(((size_t)(b_ * Hh + h)) * Tt + t_) * Dd + d] = v0;
                }
                {
                    const int b_ = mB >> 11, t_ = mB & 2047;
                    *(float2*)&outp[(((size_t)(b_ * Hh + h)) * Tt + t_) * Dd + d] = v1;
                }
            } else {
                *(float2*)&Out[(size_t)mA * N + n] = v0;
                *(float2*)&Out[(size_t)mB * N + n] = v1;
            }
        }
    }
}

// ---------------------------------------------------------------------------
// Flash attention (causal), fp32 — unchanged (near FFMA peak for its pipe).
// ---------------------------------------------------------------------------
#define SM_Q 0
#define SM_KP (64 * 68)
#define SM_V (2 * 64 * 68)
#define ATTN_SMEM (3 * 64 * 68 * 4)

__device__ __forceinline__ float rmax16(float v) {
#pragma unroll
    for (int off = 8; off; off >>= 1)
        v = fmaxf(v, __shfl_xor_sync(0xffffffffu, v, off));
    return v;
}
__device__ __forceinline__ float rsum16(float v) {
#pragma unroll
    for (int off = 8; off; off >>= 1)
        v += __shfl_xor_sync(0xffffffffu, v, off);
    return v;
}

__global__ __launch_bounds__(256, 1) void attn_kernel()
{
    extern __shared__ float sm[];
    float* Qs = sm + SM_Q;
    float* KPs = sm + SM_KP;
    float* Vs = sm + SM_V;

    const int tid = threadIdx.x;
    const int tx = tid & 15, ty = tid >> 4;
    const int bh = blockIdx.y;
    const int qt = gridDim.x - 1 - blockIdx.x;

    const float* Qg = g_q + (size_t)bh * Tt * Dd;
    const float* Kg = g_k + (size_t)bh * Tt * Dd;
    const float* Vg = g_v + (size_t)bh * Tt * Dd;

    const int lr = tid >> 2;
    const int lc = (tid & 3) << 4;

    {
        const float* src = Qg + ((size_t)qt * 64 + lr) * Dd + lc;
#pragma unroll
        for (int q = 0; q < 4; q++) {
            float4 v = *(const float4*)(src + q * 4);
            *(float4*)&Qs[lr * 68 + lc + q * 4] = v;
        }
    }

    float m_r[4], l_r[4], acc[4][4];
#pragma unroll
    for (int i = 0; i < 4; i++) {
        m_r[i] = -1e30f;
        l_r[i] = 0.0f;
#pragma unroll
        for (int j = 0; j < 4; j++) acc[i][j] = 0.0f;
    }

    for (int kt = 0; kt <= qt; kt++) {
        __syncthreads();
        {
            const float* ks = Kg + ((size_t)kt * 64 + lr) * Dd + lc;
            const float* vs = Vg + ((size_t)kt * 64 + lr) * Dd + lc;
#pragma unroll
            for (int q = 0; q < 4; q++) {
                int d0 = lc + q * 4;
                float4 kv = *(const float4*)(ks + q * 4);
                KPs[(d0 + 0) * 68 + lr] = kv.x;
                KPs[(d0 + 1) * 68 + lr] = kv.y;
                KPs[(d0 + 2) * 68 + lr] = kv.z;
                KPs[(d0 + 3) * 68 + lr] = kv.w;
                float4 vv = *(const float4*)(vs + q * 4);
                *(float4*)&Vs[lr * 68 + d0] = vv;
            }
        }
        __syncthreads();

        float s[4][4];
#pragma unroll
        for (int i = 0; i < 4; i++)
#pragma unroll
            for (int j = 0; j < 4; j++) s[i][j] = 0.0f;
#pragma unroll 8
        for (int kd = 0; kd < 64; kd++) {
            float a0 = Qs[(ty * 4 + 0) * 68 + kd];
            float a1 = Qs[(ty * 4 + 1) * 68 + kd];
            float a2 = Qs[(ty * 4 + 2) * 68 + kd];
            float a3 = Qs[(ty * 4 + 3) * 68 + kd];
            float4 b = *(const float4*)&KPs[kd * 68 + tx * 4];
            s[0][0] += a0 * b.x; s[0][1] += a0 * b.y; s[0][2] += a0 * b.z; s[0][3] += a0 * b.w;
            s[1][0] += a1 * b.x; s[1][1] += a1 * b.y; s[1][2] += a1 * b.z; s[1][3] += a1 * b.w;
            s[2][0] += a2 * b.x; s[2][1] += a2 * b.y; s[2][2] += a2 * b.z; s[2][3] += a2 * b.w;
            s[3][0] += a3 * b.x; s[3][1] += a3 * b.y; s[3][2] += a3 * b.z; s[3][3] += a3 * b.w;
        }

        const float scale = 0.125f;
        if (kt == qt) {
#pragma unroll
            for (int i = 0; i < 4; i++)
#pragma unroll
                for (int j = 0; j < 4; j++)
                    s[i][j] = (tx * 4 + j > ty * 4 + i) ? -1e30f : s[i][j] * scale;
        } else {
#pragma unroll
            for (int i = 0; i < 4; i++)
#pragma unroll
                for (int j = 0; j < 4; j++) s[i][j] *= scale;
        }

        float mnew[4], corr[4], rs[4];
#pragma unroll
        for (int i = 0; i < 4; i++) {
            float m = fmaxf(fmaxf(s[i][0], s[i][1]), fmaxf(s[i][2], s[i][3]));
            m = rmax16(m);
            mnew[i] = fmaxf(m_r[i], m);
            corr[i] = __expf(m_r[i] - mnew[i]);
            float sum = 0.0f;
#pragma unroll
            for (int j = 0; j < 4; j++) {
                s[i][j] = __expf(s[i][j] - mnew[i]);
                sum += s[i][j];
            }
            rs[i] = rsum16(sum);
            l_r[i] = l_r[i] * corr[i] + rs[i];
            m_r[i] = mnew[i];
#pragma unroll
            for (int j = 0; j < 4; j++) acc[i][j] *= corr[i];
        }

        __syncthreads();
#pragma unroll
        for (int i = 0; i < 4; i++) {
            float4 p;
            p.x = s[i][0]; p.y = s[i][1]; p.z = s[i][2]; p.w = s[i][3];
            *(float4*)&KPs[(ty * 4 + i) * 68 + tx * 4] = p;
        }
        __syncthreads();

#pragma unroll 8
        for (int kc = 0; kc < 64; kc++) {
            float p0 = KPs[(ty * 4 + 0) * 68 + kc];
            float p1 = KPs[(ty * 4 + 1) * 68 + kc];
            float p2 = KPs[(ty * 4 + 2) * 68 + kc];
            float p3 = KPs[(ty * 4 + 3) * 68 + kc];
            float4 v = *(const float4*)&Vs[kc * 68 + tx * 4];
            acc[0][0] += p0 * v.x; acc[0][1] += p0 * v.y; acc[0][2] += p0 * v.z; acc[0][3] += p0 * v.w;
            acc[1][0] += p1 * v.x; acc[1][1] += p1 * v.y; acc[1][2] += p1 * v.z; acc[1][3] += p1 * v.w;
            acc[2][0] += p2 * v.x; acc[2][1] += p2 * v.y; acc[2][2] += p2 * v.z; acc[2][3] += p2 * v.w;
            acc[3][0] += p3 * v.x; acc[3][1] += p3 * v.y; acc[3][2] += p3 * v.z; acc[3][3] += p3 * v.w;
        }
    }

    const int b = bh / Hh, h = bh % Hh;
#pragma unroll
    for (int i = 0; i < 4; i++) {
        float inv = 1.0f / l_r[i];
        int t = qt * 64 + ty * 4 + i;
        float4 o;
        o.x = acc[i][0] * inv;
        o.y = acc[i][1] * inv;
        o.z = acc[i][2] * inv;
        o.w = acc[i][3] * inv;
        *(float4*)&g_y[((size_t)b * Tt + t) * Cc + h * Dd + tx * 4] = o;
    }
}

// ---------------------------------------------------------------------------

extern "C" void kernel_launch(void* const* d_in, const int* in_sizes, int n_in,
                              void* d_out, int out_size)
{
    const float* x = (const float*)d_in[0];
    const float* w_qkv = (const float*)d_in[1];
    const float* b_qkv = (const float*)d_in[2];
    const float* w_proj = (const float*)d_in[3];
    const float* b_proj = (const float*)d_in[4];
    float* out = (float*)d_out;

    cudaFuncSetAttribute(attn_kernel, cudaFuncAttributeMaxDynamicSharedMemorySize, ATTN_SMEM);

    // QKV GEMM (TF32 MMA): [8192,1024] x [1024,3072] -> scatter q/k/v
    gemm_tc<3 * Cc, true><<<dim3(24, 64), 256>>>(x, w_qkv, b_qkv, nullptr);
    // Flash attention (fp32): g_q/g_k/g_v -> g_y
    attn_kernel<<<dim3(Tt / 64, Bb * Hh), 256, ATTN_SMEM>>>();
    // Proj GEMM (TF32 MMA): g_y [8192,1024] x [1024,1024] + bias -> out
    gemm_tc<Cc, false><<<dim3(8, 64), 256>>>(nullptr, w_proj, b_proj, out);
}

// round 7
// speedup vs baseline: 2.3986x; 1.6042x over previous
#include <cuda_runtime.h>
#include <math.h>
#include <stdint.h>

#define Bb 4
#define Tt 2048
#define Cc 1024
#define Hh 16
#define Dd 64

// Scratch (alloc-free rule: __device__ globals)
__device__ float g_q[(size_t)Bb*Hh*Tt*Dd];
__device__ float g_k[(size_t)Bb*Hh*Tt*Dd];
__device__ float g_v[(size_t)Bb*Hh*Tt*Dd];
__device__ float g_y[(size_t)Bb*Tt*Cc];

__device__ __forceinline__ float totf32(float x) {
    uint32_t u;
    asm("cvt.rna.tf32.f32 %0, %1;" : "=r"(u) : "f"(x));
    return __uint_as_float(u);
}

__device__ __forceinline__ void mma_tf32(float4& c,
    uint32_t a0, uint32_t a1, uint32_t a2, uint32_t a3,
    uint32_t b0, uint32_t b1)
{
    asm volatile(
        "mma.sync.aligned.m16n8k8.row.col.f32.tf32.tf32.f32 "
        "{%0,%1,%2,%3}, {%4,%5,%6,%7}, {%8,%9}, {%0,%1,%2,%3};\n"
        : "+f"(c.x), "+f"(c.y), "+f"(c.z), "+f"(c.w)
        : "r"(a0), "r"(a1), "r"(a2), "r"(a3), "r"(b0), "r"(b1));
}

// ---------------------------------------------------------------------------
// TF32 GEMM, double-buffered smem (2 stages, ONE sync per BK=32 tile).
// 128x128 CTA tile, 256 threads (8 warps 2x4), warp tile 64x32.
// ---------------------------------------------------------------------------
#define GSZ (32 * 136)
#define GEMM_SMEM (4 * GSZ * 4)  // 2 stages x (A+B)

template<int N, bool SCATTER>
__global__ __launch_bounds__(256, 1) void gemm_tc(
    const float* __restrict__ A, const float* __restrict__ W,
    const float* __restrict__ bias, float* __restrict__ Out)
{
    const int K = Cc;
    extern __shared__ float dsm[];

    const int tid = threadIdx.x;
    const int wid = tid >> 5, lane = tid & 31;
    const int warp_m = wid >> 2, warp_n = wid & 3;
    const int g = lane >> 2, r = lane & 3;

    const int mBlk = blockIdx.y * 128, nBlk = blockIdx.x * 128;
    const float* Abase = SCATTER ? A : g_y;

    const int am = tid >> 1, ak = (tid & 1) * 16;
    const float* aptr = Abase + (size_t)(mBlk + am) * K + ak;
    const int bk = tid >> 3, bn = (tid & 7) * 16;
    const float* wptr = W + (size_t)bk * N + nBlk + bn;

    float4 aReg[4], bReg[4];
#pragma unroll
    for (int i = 0; i < 4; i++) aReg[i] = *(const float4*)(aptr + i * 4);
#pragma unroll
    for (int i = 0; i < 4; i++) bReg[i] = *(const float4*)(wptr + i * 4);

    float4 acc[4][4];
#pragma unroll
    for (int i = 0; i < 4; i++)
#pragma unroll
        for (int j = 0; j < 4; j++) acc[i][j] = make_float4(0.f, 0.f, 0.f, 0.f);

    // STS tile 0 into stage 0
    {
        float* As = dsm;
        float* Bs = dsm + 2 * GSZ;
#pragma unroll
        for (int i = 0; i < 4; i++) {
            As[(ak + i * 4 + 0) * 136 + am] = totf32(aReg[i].x);
            As[(ak + i * 4 + 1) * 136 + am] = totf32(aReg[i].y);
            As[(ak + i * 4 + 2) * 136 + am] = totf32(aReg[i].z);
            As[(ak + i * 4 + 3) * 136 + am] = totf32(aReg[i].w);
        }
#pragma unroll
        for (int i = 0; i < 4; i++) {
            float4 t;
            t.x = totf32(bReg[i].x); t.y = totf32(bReg[i].y);
            t.z = totf32(bReg[i].z); t.w = totf32(bReg[i].w);
            *(float4*)&Bs[bk * 136 + bn + i * 4] = t;
        }
    }
    __syncthreads();

    const int NT = K / 32;
    for (int kt = 0; kt < NT; kt++) {
        // issue global loads for next tile early (latency hidden by MMAs)
        if (kt + 1 < NT) {
            aptr += 32;
            wptr += (size_t)32 * N;
#pragma unroll
            for (int i = 0; i < 4; i++) aReg[i] = *(const float4*)(aptr + i * 4);
#pragma unroll
            for (int i = 0; i < 4; i++) bReg[i] = *(const float4*)(wptr + i * 4);
        }

        const float* As = dsm + (kt & 1) * GSZ;
        const float* Bs = dsm + 2 * GSZ + (kt & 1) * GSZ;

#pragma unroll
        for (int kk = 0; kk < 4; kk++) {
            const int k = kk * 8;
            uint32_t af[4][4], bf[4][2];
#pragma unroll
            for (int mt = 0; mt < 4; mt++) {
                const int m0 = warp_m * 64 + mt * 16 + g;
                af[mt][0] = __float_as_uint(As[(k + r) * 136 + m0]);
                af[mt][1] = __float_as_uint(As[(k + r) * 136 + m0 + 8]);
                af[mt][2] = __float_as_uint(As[(k + r + 4) * 136 + m0]);
                af[mt][3] = __float_as_uint(As[(k + r + 4) * 136 + m0 + 8]);
            }
#pragma unroll
            for (int nt = 0; nt < 4; nt++) {
                const int n0 = warp_n * 32 + nt * 8 + g;
                bf[nt][0] = __float_as_uint(Bs[(k + r) * 136 + n0]);
                bf[nt][1] = __float_as_uint(Bs[(k + r + 4) * 136 + n0]);
            }
#pragma unroll
            for (int mt = 0; mt < 4; mt++)
#pragma unroll
                for (int nt = 0; nt < 4; nt++)
                    mma_tf32(acc[mt][nt],
                             af[mt][0], af[mt][1], af[mt][2], af[mt][3],
                             bf[nt][0], bf[nt][1]);
        }

        // STS next tile into the other stage (its readers finished last iter)
        if (kt + 1 < NT) {
            float* Asw = dsm + ((kt + 1) & 1) * GSZ;
            float* Bsw = dsm + 2 * GSZ + ((kt + 1) & 1) * GSZ;
#pragma unroll
            for (int i = 0; i < 4; i++) {
                Asw[(ak + i * 4 + 0) * 136 + am] = totf32(aReg[i].x);
                Asw[(ak + i * 4 + 1) * 136 + am] = totf32(aReg[i].y);
                Asw[(ak + i * 4 + 2) * 136 + am] = totf32(aReg[i].z);
                Asw[(ak + i * 4 + 3) * 136 + am] = totf32(aReg[i].w);
            }
#pragma unroll
            for (int i = 0; i < 4; i++) {
                float4 t;
                t.x = totf32(bReg[i].x); t.y = totf32(bReg[i].y);
                t.z = totf32(bReg[i].z); t.w = totf32(bReg[i].w);
                *(float4*)&Bsw[bk * 136 + bn + i * 4] = t;
            }
        }
        __syncthreads();
    }

    // Epilogue
#pragma unroll
    for (int mt = 0; mt < 4; mt++) {
        const int mA = mBlk + warp_m * 64 + mt * 16 + g;
        const int mB = mA + 8;
#pragma unroll
        for (int nt = 0; nt < 4; nt++) {
            const int n = nBlk + warp_n * 32 + nt * 8 + 2 * r;
            const float b0 = bias[n], b1 = bias[n + 1];
            float2 v0 = make_float2(acc[mt][nt].x + b0, acc[mt][nt].y + b1);
            float2 v1 = make_float2(acc[mt][nt].z + b0, acc[mt][nt].w + b1);
            if (SCATTER) {
                const int which = n >> 10;
                const int h = (n & 1023) >> 6;
                const int d = n & 63;
                float* outp = (which == 0) ? g_q : ((which == 1) ? g_k : g_v);
                {
                    const int b_ = mA >> 11, t_ = mA & 2047;
                    *(float2*)&outp[(((size_t)(b_ * Hh + h)) * Tt + t_) * Dd + d] = v0;
                }
                {
                    const int b_ = mB >> 11, t_ = mB & 2047;
                    *(float2*)&outp[(((size_t)(b_ * Hh + h)) * Tt + t_) * Dd + d] = v1;
                }
            } else {
                *(float2*)&Out[(size_t)mA * N + n] = v0;
                *(float2*)&Out[(size_t)mB * N + n] = v1;
            }
        }
    }
}

// ---------------------------------------------------------------------------
// Flash attention (causal) with TF32 tensor-core MMAs.
// CTA: 256 threads (8 warps), q-tile = 128 rows (16 rows/warp), k-block = 64.
// Q fragments register-resident for the whole loop (scale folded in).
// K/V in smem [row][d] stride 72 -> conflict-free fragment LDS.
// P round-trips through warp-private smem rows (only __syncwarp needed).
// ---------------------------------------------------------------------------
#define APAD 72
#define ATTN_SMEM ((2 * 64 * APAD + 128 * APAD) * 4)  // Ks + Vs + Ps = 73728 B

__global__ __launch_bounds__(256, 1) void attn_tc()
{
    extern __shared__ float sm[];
    float* Ks = sm;                    // [64][72]
    float* Vs = sm + 64 * APAD;        // [64][72]
    float* Ps = sm + 2 * 64 * APAD;    // [128][72] (also Q staging)

    const int tid = threadIdx.x;
    const int wid = tid >> 5, lane = tid & 31;
    const int g = lane >> 2, r = lane & 3;
    const int bh = blockIdx.y;
    const int qt = gridDim.x - 1 - blockIdx.x;  // heavy tiles first

    const float* Qg = g_q + (size_t)bh * Tt * Dd;
    const float* Kg = g_k + (size_t)bh * Tt * Dd;
    const float* Vg = g_v + (size_t)bh * Tt * Dd;

    // ---- Stage Q tile [128][64] into Ps, then load fragments to registers
    {
        const int qr = tid >> 1, qc = (tid & 1) * 32;
        const float* qsrc = Qg + ((size_t)qt * 128 + qr) * Dd + qc;
#pragma unroll
        for (int i = 0; i < 8; i++)
            *(float4*)&Ps[qr * APAD + qc + i * 4] = *(const float4*)(qsrc + i * 4);
    }
    __syncthreads();

    uint32_t qf[8][4];  // a-frags per 8-d chunk, softmax scale folded in
    {
        const int row0 = wid * 16 + g;
#pragma unroll
        for (int kd = 0; kd < 8; kd++) {
            qf[kd][0] = __float_as_uint(totf32(Ps[row0 * APAD + kd * 8 + r] * 0.125f));
            qf[kd][1] = __float_as_uint(totf32(Ps[(row0 + 8) * APAD + kd * 8 + r] * 0.125f));
            qf[kd][2] = __float_as_uint(totf32(Ps[row0 * APAD + kd * 8 + r + 4] * 0.125f));
            qf[kd][3] = __float_as_uint(totf32(Ps[(row0 + 8) * APAD + kd * 8 + r + 4] * 0.125f));
        }
    }

    float m0 = -1e30f, m1 = -1e30f, l0 = 0.f, l1 = 0.f;
    float4 o[8];
#pragma unroll
    for (int i = 0; i < 8; i++) o[i] = make_float4(0.f, 0.f, 0.f, 0.f);

    const int row0g = qt * 128 + wid * 16 + g;
    const int row1g = row0g + 8;
    const int ktmax = 2 * qt + 1;

    for (int kt = 0; kt <= ktmax; kt++) {
        __syncthreads();  // prior S/PV reads of Ks/Vs done (also covers Q staging)
        // load K,V block [64][64] with rna tf32 at STS
        {
            const int krow = tid >> 2, kcol = (tid & 3) * 16;
            const float* ks = Kg + ((size_t)kt * 64 + krow) * Dd + kcol;
            const float* vs = Vg + ((size_t)kt * 64 + krow) * Dd + kcol;
#pragma unroll
            for (int i = 0; i < 4; i++) {
                float4 kv = *(const float4*)(ks + i * 4);
                float4 vv = *(const float4*)(vs + i * 4);
                float4 tk, tv;
                tk.x = totf32(kv.x); tk.y = totf32(kv.y); tk.z = totf32(kv.z); tk.w = totf32(kv.w);
                tv.x = totf32(vv.x); tv.y = totf32(vv.y); tv.z = totf32(vv.z); tv.w = totf32(vv.w);
                *(float4*)&Ks[krow * APAD + kcol + i * 4] = tk;
                *(float4*)&Vs[krow * APAD + kcol + i * 4] = tv;
            }
        }
        __syncthreads();

        // ---- S = (Q*scale) K^T   [16 x 64 per warp]
        float4 s[8];
#pragma unroll
        for (int nt = 0; nt < 8; nt++) s[nt] = make_float4(0.f, 0.f, 0.f, 0.f);
#pragma unroll
        for (int kd = 0; kd < 8; kd++) {
#pragma unroll
            for (int nt = 0; nt < 8; nt++) {
                uint32_t b0 = __float_as_uint(Ks[(nt * 8 + g) * APAD + kd * 8 + r]);
                uint32_t b1 = __float_as_uint(Ks[(nt * 8 + g) * APAD + kd * 8 + r + 4]);
                mma_tf32(s[nt], qf[kd][0], qf[kd][1], qf[kd][2], qf[kd][3], b0, b1);
            }
        }

        // ---- causal mask (only near-diagonal blocks)
        if (kt * 64 + 63 > qt * 128 + wid * 16) {
#pragma unroll
            for (int nt = 0; nt < 8; nt++) {
                const int c0 = kt * 64 + nt * 8 + 2 * r, c1 = c0 + 1;
                if (c0 > row0g) s[nt].x = -1e30f;
                if (c1 > row0g) s[nt].y = -1e30f;
                if (c0 > row1g) s[nt].z = -1e30f;
                if (c1 > row1g) s[nt].w = -1e30f;
            }
        }

        // ---- online softmax (rows g and g+8; quad reduction over r)
        float mx0 = -1e30f, mx1 = -1e30f;
#pragma unroll
        for (int nt = 0; nt < 8; nt++) {
            mx0 = fmaxf(mx0, fmaxf(s[nt].x, s[nt].y));
            mx1 = fmaxf(mx1, fmaxf(s[nt].z, s[nt].w));
        }
#pragma unroll
        for (int off = 1; off <= 2; off <<= 1) {
            mx0 = fmaxf(mx0, __shfl_xor_sync(0xffffffffu, mx0, off));
            mx1 = fmaxf(mx1, __shfl_xor_sync(0xffffffffu, mx1, off));
        }
        const float mn0 = fmaxf(m0, mx0), mn1 = fmaxf(m1, mx1);
        const float corr0 = __expf(m0 - mn0), corr1 = __expf(m1 - mn1);
        float sum0 = 0.f, sum1 = 0.f;
#pragma unroll
        for (int nt = 0; nt < 8; nt++) {
            s[nt].x = __expf(s[nt].x - mn0); sum0 += s[nt].x;
            s[nt].y = __expf(s[nt].y - mn0); sum0 += s[nt].y;
            s[nt].z = __expf(s[nt].z - mn1); sum1 += s[nt].z;
            s[nt].w = __expf(s[nt].w - mn1); sum1 += s[nt].w;
        }
#pragma unroll
        for (int off = 1; off <= 2; off <<= 1) {
            sum0 += __shfl_xor_sync(0xffffffffu, sum0, off);
            sum1 += __shfl_xor_sync(0xffffffffu, sum1, off);
        }
        l0 = l0 * corr0 + sum0; m0 = mn0;
        l1 = l1 * corr1 + sum1; m1 = mn1;
#pragma unroll
        for (int nt = 0; nt < 8; nt++) {
            o[nt].x *= corr0; o[nt].y *= corr0;
            o[nt].z *= corr1; o[nt].w *= corr1;
        }

        // ---- P -> warp-private smem rows (tf32), then PV MMAs
        {
            const int pr0 = wid * 16 + g;
#pragma unroll
            for (int nt = 0; nt < 8; nt++) {
                Ps[pr0 * APAD + nt * 8 + 2 * r]       = totf32(s[nt].x);
                Ps[pr0 * APAD + nt * 8 + 2 * r + 1]   = totf32(s[nt].y);
                Ps[(pr0 + 8) * APAD + nt * 8 + 2 * r]     = totf32(s[nt].z);
                Ps[(pr0 + 8) * APAD + nt * 8 + 2 * r + 1] = totf32(s[nt].w);
            }
        }
        __syncwarp();
#pragma unroll
        for (int kk = 0; kk < 8; kk++) {
            const int pr0 = wid * 16 + g;
            uint32_t a0 = __float_as_uint(Ps[pr0 * APAD + kk * 8 + r]);
            uint32_t a1 = __float_as_uint(Ps[(pr0 + 8) * APAD + kk * 8 + r]);
            uint32_t a2 = __float_as_uint(Ps[pr0 * APAD + kk * 8 + r + 4]);
            uint32_t a3 = __float_as_uint(Ps[(pr0 + 8) * APAD + kk * 8 + r + 4]);
#pragma unroll
            for (int nt = 0; nt < 8; nt++) {
                uint32_t b0 = __float_as_uint(Vs[(kk * 8 + r) * APAD + nt * 8 + g]);
                uint32_t b1 = __float_as_uint(Vs[(kk * 8 + r + 4) * APAD + nt * 8 + g]);
                mma_tf32(o[nt], a0, a1, a2, a3, b0, b1);
            }
        }
        __syncwarp();  // PV reads done before next iter's Ps writes
    }

    // ---- normalize + write y [B,T,C]
    const float inv0 = 1.0f / l0, inv1 = 1.0f / l1;
    const int b = bh >> 4, h = bh & 15;
#pragma unroll
    for (int nt = 0; nt < 8; nt++) {
        const int col = h * 64 + nt * 8 + 2 * r;
        float2 v0 = make_float2(o[nt].x * inv0, o[nt].y * inv0);
        float2 v1 = make_float2(o[nt].z * inv1, o[nt].w * inv1);
        *(float2*)&g_y[((size_t)b * Tt + row0g) * Cc + col] = v0;
        *(float2*)&g_y[((size_t)b * Tt + row1g) * Cc + col] = v1;
    }
}

// ---------------------------------------------------------------------------

extern "C" void kernel_launch(void* const* d_in, const int* in_sizes, int n_in,
                              void* d_out, int out_size)
{
    const float* x = (const float*)d_in[0];
    const float* w_qkv = (const float*)d_in[1];
    const float* b_qkv = (const float*)d_in[2];
    const float* w_proj = (const float*)d_in[3];
    const float* b_proj = (const float*)d_in[4];
    float* out = (float*)d_out;

    cudaFuncSetAttribute(gemm_tc<3 * Cc, true>,
                         cudaFuncAttributeMaxDynamicSharedMemorySize, GEMM_SMEM);
    cudaFuncSetAttribute(gemm_tc<Cc, false>,
                         cudaFuncAttributeMaxDynamicSharedMemorySize, GEMM_SMEM);
    cudaFuncSetAttribute(attn_tc,
                         cudaFuncAttributeMaxDynamicSharedMemorySize, ATTN_SMEM);

    // QKV GEMM (TF32 MMA, double-buffered): scatter q/k/v
    gemm_tc<3 * Cc, true><<<dim3(24, 64), 256, GEMM_SMEM>>>(x, w_qkv, b_qkv, nullptr);
    // Flash attention (TF32 MMA): g_q/g_k/g_v -> g_y
    attn_tc<<<dim3(Tt / 128, Bb * Hh), 256, ATTN_SMEM>>>();
    // Proj GEMM (TF32 MMA, double-buffered): g_y x w_proj + bias -> out
    gemm_tc<Cc, false><<<dim3(8, 64), 256, GEMM_SMEM>>>(nullptr, w_proj, b_proj, out);
}

// round 8
// speedup vs baseline: 2.5686x; 1.0709x over previous
#include <cuda_runtime.h>
#include <math.h>
#include <stdint.h>

#define Bb 4
#define Tt 2048
#define Cc 1024
#define Hh 16
#define Dd 64

// Scratch (alloc-free rule: __device__ globals)
__device__ float g_q[(size_t)Bb*Hh*Tt*Dd];
__device__ float g_k[(size_t)Bb*Hh*Tt*Dd];
__device__ float g_v[(size_t)Bb*Hh*Tt*Dd];
__device__ float g_y[(size_t)Bb*Tt*Cc];

__device__ __forceinline__ float totf32(float x) {
    uint32_t u;
    asm("cvt.rna.tf32.f32 %0, %1;" : "=r"(u) : "f"(x));
    return __uint_as_float(u);
}
__device__ __forceinline__ uint32_t tfbits(float x) {
    uint32_t u;
    asm("cvt.rna.tf32.f32 %0, %1;" : "=r"(u) : "f"(x));
    return u;
}

__device__ __forceinline__ void mma_tf32(float4& c,
    uint32_t a0, uint32_t a1, uint32_t a2, uint32_t a3,
    uint32_t b0, uint32_t b1)
{
    asm volatile(
        "mma.sync.aligned.m16n8k8.row.col.f32.tf32.tf32.f32 "
        "{%0,%1,%2,%3}, {%4,%5,%6,%7}, {%8,%9}, {%0,%1,%2,%3};\n"
        : "+f"(c.x), "+f"(c.y), "+f"(c.z), "+f"(c.w)
        : "r"(a0), "r"(a1), "r"(a2), "r"(a3), "r"(b0), "r"(b1));
}

__device__ __forceinline__ void cp16(float* smem_dst, const float* gmem_src) {
    uint32_t s = (uint32_t)__cvta_generic_to_shared(smem_dst);
    asm volatile("cp.async.cg.shared.global [%0], [%1], 16;\n" :: "r"(s), "l"(gmem_src));
}
#define CP_COMMIT() asm volatile("cp.async.commit_group;\n" ::: "memory")
#define CP_WAIT(n)  asm volatile("cp.async.wait_group %0;\n" :: "n"(n) : "memory")

// ---------------------------------------------------------------------------
// TF32 GEMM with cp.async double-buffering, 2 CTAs/SM.
// 128x128 CTA tile, BK=32, 256 threads (8 warps 2x4), warp tile 64x32.
// A in smem [m][k] stride 36; B in smem [k][n] stride 136. Raw fp32 in smem;
// rna->tf32 conversion applied at fragment load.
// ---------------------------------------------------------------------------
#define ASTG (128 * 36)
#define BSTG (32 * 136)
#define GEMM_SMEM ((2 * ASTG + 2 * BSTG) * 4)  // 71680 B

template<int N, bool SCATTER>
__global__ __launch_bounds__(256, 2) void gemm_tc(
    const float* __restrict__ A, const float* __restrict__ W,
    const float* __restrict__ bias, float* __restrict__ Out)
{
    const int K = Cc;
    extern __shared__ float dsm[];
    float* Abuf = dsm;              // 2 x [128][36]
    float* Bbuf = dsm + 2 * ASTG;   // 2 x [32][136]

    const int tid = threadIdx.x;
    const int wid = tid >> 5, lane = tid & 31;
    const int warp_m = wid >> 2, warp_n = wid & 3;
    const int g = lane >> 2, r = lane & 3;

    const int mBlk = blockIdx.y * 128, nBlk = blockIdx.x * 128;
    const float* Abase = SCATTER ? A : g_y;

    // cp.async coords: A row am, 16-float span at ac; B row bk, 16-float span at bn
    const int am = tid >> 1, ac = (tid & 1) * 16;
    const int bk = tid >> 3, bn = (tid & 7) * 16;
    const float* aptr = Abase + (size_t)(mBlk + am) * K + ac;
    const float* wptr = W + (size_t)bk * N + nBlk + bn;

    const int NT = K / 32;  // 32

#define ISSUE_TILE(kt, stg)                                                  \
    do {                                                                     \
        float* ad = Abuf + (stg) * ASTG + am * 36 + ac;                      \
        const float* as = aptr + (kt) * 32;                                  \
        _Pragma("unroll")                                                    \
        for (int i = 0; i < 4; i++) cp16(ad + i * 4, as + i * 4);            \
        float* bd = Bbuf + (stg) * BSTG + bk * 136 + bn;                     \
        const float* bs = wptr + (size_t)(kt) * 32 * N;                      \
        _Pragma("unroll")                                                    \
        for (int i = 0; i < 4; i++) cp16(bd + i * 4, bs + i * 4);            \
    } while (0)

    ISSUE_TILE(0, 0); CP_COMMIT();
    ISSUE_TILE(1, 1); CP_COMMIT();

    float4 acc[4][4];
#pragma unroll
    for (int i = 0; i < 4; i++)
#pragma unroll
        for (int j = 0; j < 4; j++) acc[i][j] = make_float4(0.f, 0.f, 0.f, 0.f);

    CP_WAIT(1);
    __syncthreads();

    for (int kt = 0; kt < NT; kt++) {
        const float* As = Abuf + (kt & 1) * ASTG;
        const float* Bs = Bbuf + (kt & 1) * BSTG;

#pragma unroll
        for (int kk = 0; kk < 4; kk++) {
            const int k = kk * 8;
            uint32_t af[4][4], bf[4][2];
#pragma unroll
            for (int mt = 0; mt < 4; mt++) {
                const int m0 = warp_m * 64 + mt * 16 + g;
                af[mt][0] = tfbits(As[m0 * 36 + k + r]);
                af[mt][1] = tfbits(As[(m0 + 8) * 36 + k + r]);
                af[mt][2] = tfbits(As[m0 * 36 + k + r + 4]);
                af[mt][3] = tfbits(As[(m0 + 8) * 36 + k + r + 4]);
            }
#pragma unroll
            for (int nt = 0; nt < 4; nt++) {
                const int n0 = warp_n * 32 + nt * 8 + g;
                bf[nt][0] = tfbits(Bs[(k + r) * 136 + n0]);
                bf[nt][1] = tfbits(Bs[(k + r + 4) * 136 + n0]);
            }
#pragma unroll
            for (int mt = 0; mt < 4; mt++)
#pragma unroll
                for (int nt = 0; nt < 4; nt++)
                    mma_tf32(acc[mt][nt],
                             af[mt][0], af[mt][1], af[mt][2], af[mt][3],
                             bf[nt][0], bf[nt][1]);
        }

        __syncthreads();  // all warps done reading stage kt&1
        if (kt + 2 < NT) { ISSUE_TILE(kt + 2, kt & 1); CP_COMMIT(); }
        if (kt + 1 < NT) {
            if (kt + 2 < NT) { CP_WAIT(1); } else { CP_WAIT(0); }
            __syncthreads();
        }
    }
#undef ISSUE_TILE

    // Epilogue
#pragma unroll
    for (int mt = 0; mt < 4; mt++) {
        const int mA = mBlk + warp_m * 64 + mt * 16 + g;
        const int mB = mA + 8;
#pragma unroll
        for (int nt = 0; nt < 4; nt++) {
            const int n = nBlk + warp_n * 32 + nt * 8 + 2 * r;
            const float b0 = bias[n], b1 = bias[n + 1];
            float2 v0 = make_float2(acc[mt][nt].x + b0, acc[mt][nt].y + b1);
            float2 v1 = make_float2(acc[mt][nt].z + b0, acc[mt][nt].w + b1);
            if (SCATTER) {
                const int which = n >> 10;
                const int h = (n & 1023) >> 6;
                const int d = n & 63;
                float* outp = (which == 0) ? g_q : ((which == 1) ? g_k : g_v);
                {
                    const int b_ = mA >> 11, t_ = mA & 2047;
                    *(float2*)&outp[(((size_t)(b_ * Hh + h)) * Tt + t_) * Dd + d] = v0;
                }
                {
                    const int b_ = mB >> 11, t_ = mB & 2047;
                    *(float2*)&outp[(((size_t)(b_ * Hh + h)) * Tt + t_) * Dd + d] = v1;
                }
            } else {
                *(float2*)&Out[(size_t)mA * N + n] = v0;
                *(float2*)&Out[(size_t)mB * N + n] = v1;
            }
        }
    }
}

// ---------------------------------------------------------------------------
// Flash attention (causal), TF32 MMA — unchanged from R7 (passed, ~510us).
// ---------------------------------------------------------------------------
#define APAD 72
#define ATTN_SMEM ((2 * 64 * APAD + 128 * APAD) * 4)

__global__ __launch_bounds__(256, 1) void attn_tc()
{
    extern __shared__ float sm[];
    float* Ks = sm;
    float* Vs = sm + 64 * APAD;
    float* Ps = sm + 2 * 64 * APAD;

    const int tid = threadIdx.x;
    const int wid = tid >> 5, lane = tid & 31;
    const int g = lane >> 2, r = lane & 3;
    const int bh = blockIdx.y;
    const int qt = gridDim.x - 1 - blockIdx.x;

    const float* Qg = g_q + (size_t)bh * Tt * Dd;
    const float* Kg = g_k + (size_t)bh * Tt * Dd;
    const float* Vg = g_v + (size_t)bh * Tt * Dd;

    {
        const int qr = tid >> 1, qc = (tid & 1) * 32;
        const float* qsrc = Qg + ((size_t)qt * 128 + qr) * Dd + qc;
#pragma unroll
        for (int i = 0; i < 8; i++)
            *(float4*)&Ps[qr * APAD + qc + i * 4] = *(const float4*)(qsrc + i * 4);
    }
    __syncthreads();

    uint32_t qf[8][4];
    {
        const int row0 = wid * 16 + g;
#pragma unroll
        for (int kd = 0; kd < 8; kd++) {
            qf[kd][0] = tfbits(Ps[row0 * APAD + kd * 8 + r] * 0.125f);
            qf[kd][1] = tfbits(Ps[(row0 + 8) * APAD + kd * 8 + r] * 0.125f);
            qf[kd][2] = tfbits(Ps[row0 * APAD + kd * 8 + r + 4] * 0.125f);
            qf[kd][3] = tfbits(Ps[(row0 + 8) * APAD + kd * 8 + r + 4] * 0.125f);
        }
    }

    float m0 = -1e30f, m1 = -1e30f, l0 = 0.f, l1 = 0.f;
    float4 o[8];
#pragma unroll
    for (int i = 0; i < 8; i++) o[i] = make_float4(0.f, 0.f, 0.f, 0.f);

    const int row0g = qt * 128 + wid * 16 + g;
    const int row1g = row0g + 8;
    const int ktmax = 2 * qt + 1;

    for (int kt = 0; kt <= ktmax; kt++) {
        __syncthreads();
        {
            const int krow = tid >> 2, kcol = (tid & 3) * 16;
            const float* ks = Kg + ((size_t)kt * 64 + krow) * Dd + kcol;
            const float* vs = Vg + ((size_t)kt * 64 + krow) * Dd + kcol;
#pragma unroll
            for (int i = 0; i < 4; i++) {
                float4 kv = *(const float4*)(ks + i * 4);
                float4 vv = *(const float4*)(vs + i * 4);
                float4 tk, tv;
                tk.x = totf32(kv.x); tk.y = totf32(kv.y); tk.z = totf32(kv.z); tk.w = totf32(kv.w);
                tv.x = totf32(vv.x); tv.y = totf32(vv.y); tv.z = totf32(vv.z); tv.w = totf32(vv.w);
                *(float4*)&Ks[krow * APAD + kcol + i * 4] = tk;
                *(float4*)&Vs[krow * APAD + kcol + i * 4] = tv;
            }
        }
        __syncthreads();

        float4 s[8];
#pragma unroll
        for (int nt = 0; nt < 8; nt++) s[nt] = make_float4(0.f, 0.f, 0.f, 0.f);
#pragma unroll
        for (int kd = 0; kd < 8; kd++) {
#pragma unroll
            for (int nt = 0; nt < 8; nt++) {
                uint32_t b0 = __float_as_uint(Ks[(nt * 8 + g) * APAD + kd * 8 + r]);
                uint32_t b1 = __float_as_uint(Ks[(nt * 8 + g) * APAD + kd * 8 + r + 4]);
                mma_tf32(s[nt], qf[kd][0], qf[kd][1], qf[kd][2], qf[kd][3], b0, b1);
            }
        }

        if (kt * 64 + 63 > qt * 128 + wid * 16) {
#pragma unroll
            for (int nt = 0; nt < 8; nt++) {
                const int c0 = kt * 64 + nt * 8 + 2 * r, c1 = c0 + 1;
                if (c0 > row0g) s[nt].x = -1e30f;
                if (c1 > row0g) s[nt].y = -1e30f;
                if (c0 > row1g) s[nt].z = -1e30f;
                if (c1 > row1g) s[nt].w = -1e30f;
            }
        }

        float mx0 = -1e30f, mx1 = -1e30f;
#pragma unroll
        for (int nt = 0; nt < 8; nt++) {
            mx0 = fmaxf(mx0, fmaxf(s[nt].x, s[nt].y));
            mx1 = fmaxf(mx1, fmaxf(s[nt].z, s[nt].w));
        }
#pragma unroll
        for (int off = 1; off <= 2; off <<= 1) {
            mx0 = fmaxf(mx0, __shfl_xor_sync(0xffffffffu, mx0, off));
            mx1 = fmaxf(mx1, __shfl_xor_sync(0xffffffffu, mx1, off));
        }
        const float mn0 = fmaxf(m0, mx0), mn1 = fmaxf(m1, mx1);
        const float corr0 = __expf(m0 - mn0), corr1 = __expf(m1 - mn1);
        float sum0 = 0.f, sum1 = 0.f;
#pragma unroll
        for (int nt = 0; nt < 8; nt++) {
            s[nt].x = __expf(s[nt].x - mn0); sum0 += s[nt].x;
            s[nt].y = __expf(s[nt].y - mn0); sum0 += s[nt].y;
            s[nt].z = __expf(s[nt].z - mn1); sum1 += s[nt].z;
            s[nt].w = __expf(s[nt].w - mn1); sum1 += s[nt].w;
        }
#pragma unroll
        for (int off = 1; off <= 2; off <<= 1) {
            sum0 += __shfl_xor_sync(0xffffffffu, sum0, off);
            sum1 += __shfl_xor_sync(0xffffffffu, sum1, off);
        }
        l0 = l0 * corr0 + sum0; m0 = mn0;
        l1 = l1 * corr1 + sum1; m1 = mn1;
#pragma unroll
        for (int nt = 0; nt < 8; nt++) {
            o[nt].x *= corr0; o[nt].y *= corr0;
            o[nt].z *= corr1; o[nt].w *= corr1;
        }

        {
            const int pr0 = wid * 16 + g;
#pragma unroll
            for (int nt = 0; nt < 8; nt++) {
                Ps[pr0 * APAD + nt * 8 + 2 * r]       = totf32(s[nt].x);
                Ps[pr0 * APAD + nt * 8 + 2 * r + 1]   = totf32(s[nt].y);
                Ps[(pr0 + 8) * APAD + nt * 8 + 2 * r]     = totf32(s[nt].z);
                Ps[(pr0 + 8) * APAD + nt * 8 + 2 * r + 1] = totf32(s[nt].w);
            }
        }
        __syncwarp();
#pragma unroll
        for (int kk = 0; kk < 8; kk++) {
            const int pr0 = wid * 16 + g;
            uint32_t a0 = __float_as_uint(Ps[pr0 * APAD + kk * 8 + r]);
            uint32_t a1 = __float_as_uint(Ps[(pr0 + 8) * APAD + kk * 8 + r]);
            uint32_t a2 = __float_as_uint(Ps[pr0 * APAD + kk * 8 + r + 4]);
            uint32_t a3 = __float_as_uint(Ps[(pr0 + 8) * APAD + kk * 8 + r + 4]);
#pragma unroll
            for (int nt = 0; nt < 8; nt++) {
                uint32_t b0 = __float_as_uint(Vs[(kk * 8 + r) * APAD + nt * 8 + g]);
                uint32_t b1 = __float_as_uint(Vs[(kk * 8 + r + 4) * APAD + nt * 8 + g]);
                mma_tf32(o[nt], a0, a1, a2, a3, b0, b1);
            }
        }
        __syncwarp();
    }

    const float inv0 = 1.0f / l0, inv1 = 1.0f / l1;
    const int b = bh >> 4, h = bh & 15;
#pragma unroll
    for (int nt = 0; nt < 8; nt++) {
        const int col = h * 64 + nt * 8 + 2 * r;
        float2 v0 = make_float2(o[nt].x * inv0, o[nt].y * inv0);
        float2 v1 = make_float2(o[nt].z * inv1, o[nt].w * inv1);
        *(float2*)&g_y[((size_t)b * Tt + row0g) * Cc + col] = v0;
        *(float2*)&g_y[((size_t)b * Tt + row1g) * Cc + col] = v1;
    }
}

// ---------------------------------------------------------------------------

extern "C" void kernel_launch(void* const* d_in, const int* in_sizes, int n_in,
                              void* d_out, int out_size)
{
    const float* x = (const float*)d_in[0];
    const float* w_qkv = (const float*)d_in[1];
    const float* b_qkv = (const float*)d_in[2];
    const float* w_proj = (const float*)d_in[3];
    const float* b_proj = (const float*)d_in[4];
    float* out = (float*)d_out;

    cudaFuncSetAttribute(gemm_tc<3 * Cc, true>,
                         cudaFuncAttributeMaxDynamicSharedMemorySize, GEMM_SMEM);
    cudaFuncSetAttribute(gemm_tc<Cc, false>,
                         cudaFuncAttributeMaxDynamicSharedMemorySize, GEMM_SMEM);
    cudaFuncSetAttribute(attn_tc,
                         cudaFuncAttributeMaxDynamicSharedMemorySize, ATTN_SMEM);

    // QKV GEMM (TF32 MMA, cp.async 2-CTA): scatter q/k/v
    gemm_tc<3 * Cc, true><<<dim3(24, 64), 256, GEMM_SMEM>>>(x, w_qkv, b_qkv, nullptr);
    // Flash attention (TF32 MMA): g_q/g_k/g_v -> g_y
    attn_tc<<<dim3(Tt / 128, Bb * Hh), 256, ATTN_SMEM>>>();
    // Proj GEMM (TF32 MMA, cp.async 2-CTA): g_y x w_proj + bias -> out
    gemm_tc<Cc, false><<<dim3(8, 64), 256, GEMM_SMEM>>>(nullptr, w_proj, b_proj, out);
}

// round 11
// speedup vs baseline: 2.6054x; 1.0143x over previous
#include <cuda_runtime.h>
#include <math.h>
#include <stdint.h>

#define Bb 4
#define Tt 2048
#define Cc 1024
#define Hh 16
#define Dd 64

// Scratch (alloc-free rule: __device__ globals)
__device__ float g_q[(size_t)Bb*Hh*Tt*Dd];
__device__ float g_k[(size_t)Bb*Hh*Tt*Dd];
__device__ float g_v[(size_t)Bb*Hh*Tt*Dd];
__device__ float g_y[(size_t)Bb*Tt*Cc];      // rounded x, later rounded attn out
__device__ float g_wq[(size_t)Cc*3*Cc];      // rounded w_qkv
__device__ float g_wp[(size_t)Cc*Cc];        // rounded w_proj

__device__ __forceinline__ float totf32(float x) {
    uint32_t u;
    asm("cvt.rna.tf32.f32 %0, %1;" : "=r"(u) : "f"(x));
    return __uint_as_float(u);
}

__device__ __forceinline__ void mma_tf32(float4& c,
    uint32_t a0, uint32_t a1, uint32_t a2, uint32_t a3,
    uint32_t b0, uint32_t b1)
{
    asm volatile(
        "mma.sync.aligned.m16n8k8.row.col.f32.tf32.tf32.f32 "
        "{%0,%1,%2,%3}, {%4,%5,%6,%7}, {%8,%9}, {%0,%1,%2,%3};\n"
        : "+f"(c.x), "+f"(c.y), "+f"(c.z), "+f"(c.w)
        : "r"(a0), "r"(a1), "r"(a2), "r"(a3), "r"(b0), "r"(b1));
}

__device__ __forceinline__ void cp16(float* smem_dst, const float* gmem_src) {
    uint32_t s = (uint32_t)__cvta_generic_to_shared(smem_dst);
    asm volatile("cp.async.cg.shared.global [%0], [%1], 16;\n" :: "r"(s), "l"(gmem_src));
}
#define CP_COMMIT() asm volatile("cp.async.commit_group;\n" ::: "memory")
#define CP_WAIT(n)  asm volatile("cp.async.wait_group %0;\n" :: "n"(n) : "memory")

// ldmatrix x4 on 32-bit data: matrices (rows 0-7 @k, rows 8-15 @k, rows 0-7
// @k+4, rows 8-15 @k+4) -> exactly the tf32 a-fragment regs a0..a3.
__device__ __forceinline__ void ldsm_x4(uint32_t& r0, uint32_t& r1,
                                        uint32_t& r2, uint32_t& r3,
                                        const float* p)
{
    uint32_t a = (uint32_t)__cvta_generic_to_shared(p);
    asm volatile(
        "ldmatrix.sync.aligned.m8n8.x4.shared.b16 {%0,%1,%2,%3}, [%4];\n"
        : "=r"(r0), "=r"(r1), "=r"(r2), "=r"(r3) : "r"(a));
}

// ---------------------------------------------------------------------------
// Pre-pass: rna tf32 rounding copies (vectorized).
// ---------------------------------------------------------------------------
__global__ void round_x(const float* __restrict__ in) {
    size_t i = (size_t)blockIdx.x * blockDim.x + threadIdx.x;
    float4 v = ((const float4*)in)[i];
    float4 t;
    t.x = totf32(v.x); t.y = totf32(v.y); t.z = totf32(v.z); t.w = totf32(v.w);
    ((float4*)g_y)[i] = t;
}
__global__ void round_wq(const float* __restrict__ in) {
    size_t i = (size_t)blockIdx.x * blockDim.x + threadIdx.x;
    float4 v = ((const float4*)in)[i];
    float4 t;
    t.x = totf32(v.x); t.y = totf32(v.y); t.z = totf32(v.z); t.w = totf32(v.w);
    ((float4*)g_wq)[i] = t;
}
__global__ void round_wp(const float* __restrict__ in) {
    size_t i = (size_t)blockIdx.x * blockDim.x + threadIdx.x;
    float4 v = ((const float4*)in)[i];
    float4 t;
    t.x = totf32(v.x); t.y = totf32(v.y); t.z = totf32(v.z); t.w = totf32(v.w);
    ((float4*)g_wp)[i] = t;
}

// ---------------------------------------------------------------------------
// TF32 GEMM, cp.async double-buffered, 2 CTAs/SM. Operands pre-rounded ->
// zero cvt in hot loop; A-fragments via ldmatrix.
// ---------------------------------------------------------------------------
#define ASTG (128 * 36)
#define BSTG (32 * 136)
#define GEMM_SMEM ((2 * ASTG + 2 * BSTG) * 4)  // 71680 B

template<int N, bool SCATTER>
__global__ __launch_bounds__(256, 2) void gemm_tc(
    const float* __restrict__ bias, float* __restrict__ Out)
{
    const int K = Cc;
    extern __shared__ float dsm[];
    float* Abuf = dsm;
    float* Bbuf = dsm + 2 * ASTG;

    const int tid = threadIdx.x;
    const int wid = tid >> 5, lane = tid & 31;
    const int warp_m = wid >> 2, warp_n = wid & 3;
    const int g = lane >> 2, r = lane & 3;

    const int mBlk = blockIdx.y * 128, nBlk = blockIdx.x * 128;
    const float* Abase = g_y;
    const float* W = SCATTER ? g_wq : g_wp;

    const int am = tid >> 1, ac = (tid & 1) * 16;
    const int bk = tid >> 3, bn = (tid & 7) * 16;
    const float* aptr = Abase + (size_t)(mBlk + am) * K + ac;
    const float* wptr = W + (size_t)bk * N + nBlk + bn;

    const int NT = K / 32;

    const int lrow = lane & 15, lkh = (lane >> 4) * 4;

#define ISSUE_TILE(kt, stg)                                                  \
    do {                                                                     \
        float* ad = Abuf + (stg) * ASTG + am * 36 + ac;                      \
        const float* as = aptr + (kt) * 32;                                  \
        _Pragma("unroll")                                                    \
        for (int i = 0; i < 4; i++) cp16(ad + i * 4, as + i * 4);            \
        float* bd = Bbuf + (stg) * BSTG + bk * 136 + bn;                     \
        const float* bs = wptr + (size_t)(kt) * 32 * N;                      \
        _Pragma("unroll")                                                    \
        for (int i = 0; i < 4; i++) cp16(bd + i * 4, bs + i * 4);            \
    } while (0)

    ISSUE_TILE(0, 0); CP_COMMIT();
    ISSUE_TILE(1, 1); CP_COMMIT();

    float4 acc[4][4];
#pragma unroll
    for (int i = 0; i < 4; i++)
#pragma unroll
        for (int j = 0; j < 4; j++) acc[i][j] = make_float4(0.f, 0.f, 0.f, 0.f);

    CP_WAIT(1);
    __syncthreads();

    for (int kt = 0; kt < NT; kt++) {
        const float* As = Abuf + (kt & 1) * ASTG;
        const float* Bs = Bbuf + (kt & 1) * BSTG;

#pragma unroll
        for (int kk = 0; kk < 4; kk++) {
            const int k = kk * 8;
            uint32_t af[4][4], bf[4][2];
#pragma unroll
            for (int mt = 0; mt < 4; mt++) {
                const float* p = As + (warp_m * 64 + mt * 16 + lrow) * 36 + k + lkh;
                ldsm_x4(af[mt][0], af[mt][1], af[mt][2], af[mt][3], p);
            }
#pragma unroll
            for (int nt = 0; nt < 4; nt++) {
                const int n0 = warp_n * 32 + nt * 8 + g;
                bf[nt][0] = __float_as_uint(Bs[(k + r) * 136 + n0]);
                bf[nt][1] = __float_as_uint(Bs[(k + r + 4) * 136 + n0]);
            }
#pragma unroll
            for (int mt = 0; mt < 4; mt++)
#pragma unroll
                for (int nt = 0; nt < 4; nt++)
                    mma_tf32(acc[mt][nt],
                             af[mt][0], af[mt][1], af[mt][2], af[mt][3],
                             bf[nt][0], bf[nt][1]);
        }

        __syncthreads();
        if (kt + 2 < NT) { ISSUE_TILE(kt + 2, kt & 1); CP_COMMIT(); }
        if (kt + 1 < NT) {
            if (kt + 2 < NT) { CP_WAIT(1); } else { CP_WAIT(0); }
            __syncthreads();
        }
    }
#undef ISSUE_TILE

    // Epilogue (SCATTER stores pre-rounded tf32 for the attention MMAs)
#pragma unroll
    for (int mt = 0; mt < 4; mt++) {
        const int mA = mBlk + warp_m * 64 + mt * 16 + g;
        const int mB = mA + 8;
#pragma unroll
        for (int nt = 0; nt < 4; nt++) {
            const int n = nBlk + warp_n * 32 + nt * 8 + 2 * r;
            const float b0 = bias[n], b1 = bias[n + 1];
            if (SCATTER) {
                float2 v0 = make_float2(totf32(acc[mt][nt].x + b0), totf32(acc[mt][nt].y + b1));
                float2 v1 = make_float2(totf32(acc[mt][nt].z + b0), totf32(acc[mt][nt].w + b1));
                const int which = n >> 10;
                const int h = (n & 1023) >> 6;
                const int d = n & 63;
                float* outp = (which == 0) ? g_q : ((which == 1) ? g_k : g_v);
                {
                    const int b_ = mA >> 11, t_ = mA & 2047;
                    *(float2*)&outp[(((size_t)(b_ * Hh + h)) * Tt + t_) * Dd + d] = v0;
                }
                {
                    const int b_ = mB >> 11, t_ = mB & 2047;
                    *(float2*)&outp[(((size_t)(b_ * Hh + h)) * Tt + t_) * Dd + d] = v1;
                }
            } else {
                float2 v0 = make_float2(acc[mt][nt].x + b0, acc[mt][nt].y + b1);
                float2 v1 = make_float2(acc[mt][nt].z + b0, acc[mt][nt].w + b1);
                *(float2*)&Out[(size_t)mA * N + n] = v0;
                *(float2*)&Out[(size_t)mB * N + n] = v1;
            }
        }
    }
}

// ---------------------------------------------------------------------------
// Flash attention (causal), TF32 MMA. q/k/v pre-rounded -> staging is plain
// copies, Q frags cvt-free. Output stored rounded for the proj GEMM.
// ---------------------------------------------------------------------------
#define APAD 72
#define ATTN_SMEM ((2 * 64 * APAD + 128 * APAD) * 4)

__global__ __launch_bounds__(256, 1) void attn_tc()
{
    extern __shared__ float sm[];
    float* Ks = sm;
    float* Vs = sm + 64 * APAD;
    float* Ps = sm + 2 * 64 * APAD;

    const int tid = threadIdx.x;
    const int wid = tid >> 5, lane = tid & 31;
    const int g = lane >> 2, r = lane & 3;
    const int bh = blockIdx.y;
    const int qt = gridDim.x - 1 - blockIdx.x;

    const float* Qg = g_q + (size_t)bh * Tt * Dd;
    const float* Kg = g_k + (size_t)bh * Tt * Dd;
    const float* Vg = g_v + (size_t)bh * Tt * Dd;

    {
        const int qr = tid >> 1, qc = (tid & 1) * 32;
        const float* qsrc = Qg + ((size_t)qt * 128 + qr) * Dd + qc;
#pragma unroll
        for (int i = 0; i < 8; i++)
            *(float4*)&Ps[qr * APAD + qc + i * 4] = *(const float4*)(qsrc + i * 4);
    }
    __syncthreads();

    uint32_t qf[8][4];  // pre-rounded, *0.125f exact on tf32
    {
        const int row0 = wid * 16 + g;
#pragma unroll
        for (int kd = 0; kd < 8; kd++) {
            qf[kd][0] = __float_as_uint(Ps[row0 * APAD + kd * 8 + r] * 0.125f);
            qf[kd][1] = __float_as_uint(Ps[(row0 + 8) * APAD + kd * 8 + r] * 0.125f);
            qf[kd][2] = __float_as_uint(Ps[row0 * APAD + kd * 8 + r + 4] * 0.125f);
            qf[kd][3] = __float_as_uint(Ps[(row0 + 8) * APAD + kd * 8 + r + 4] * 0.125f);
        }
    }

    float m0 = -1e30f, m1 = -1e30f, l0 = 0.f, l1 = 0.f;
    float4 o[8];
#pragma unroll
    for (int i = 0; i < 8; i++) o[i] = make_float4(0.f, 0.f, 0.f, 0.f);

    const int row0g = qt * 128 + wid * 16 + g;
    const int row1g = row0g + 8;
    const int ktmax = 2 * qt + 1;

    for (int kt = 0; kt <= ktmax; kt++) {
        __syncthreads();
        {
            const int krow = tid >> 2, kcol = (tid & 3) * 16;
            const float* ks = Kg + ((size_t)kt * 64 + krow) * Dd + kcol;
            const float* vs = Vg + ((size_t)kt * 64 + krow) * Dd + kcol;
#pragma unroll
            for (int i = 0; i < 4; i++) {
                *(float4*)&Ks[krow * APAD + kcol + i * 4] = *(const float4*)(ks + i * 4);
                *(float4*)&Vs[krow * APAD + kcol + i * 4] = *(const float4*)(vs + i * 4);
            }
        }
        __syncthreads();

        float4 s[8];
#pragma unroll
        for (int nt = 0; nt < 8; nt++) s[nt] = make_float4(0.f, 0.f, 0.f, 0.f);
#pragma unroll
        for (int kd = 0; kd < 8; kd++) {
#pragma unroll
            for (int nt = 0; nt < 8; nt++) {
                uint32_t b0 = __float_as_uint(Ks[(nt * 8 + g) * APAD + kd * 8 + r]);
                uint32_t b1 = __float_as_uint(Ks[(nt * 8 + g) * APAD + kd * 8 + r + 4]);
                mma_tf32(s[nt], qf[kd][0], qf[kd][1], qf[kd][2], qf[kd][3], b0, b1);
            }
        }

        if (kt * 64 + 63 > qt * 128 + wid * 16) {
#pragma unroll
            for (int nt = 0; nt < 8; nt++) {
                const int c0 = kt * 64 + nt * 8 + 2 * r, c1 = c0 + 1;
                if (c0 > row0g) s[nt].x = -1e30f;
                if (c1 > row0g) s[nt].y = -1e30f;
                if (c0 > row1g) s[nt].z = -1e30f;
                if (c1 > row1g) s[nt].w = -1e30f;
            }
        }

        float mx0 = -1e30f, mx1 = -1e30f;
#pragma unroll
        for (int nt = 0; nt < 8; nt++) {
            mx0 = fmaxf(mx0, fmaxf(s[nt].x, s[nt].y));
            mx1 = fmaxf(mx1, fmaxf(s[nt].z, s[nt].w));
        }
#pragma unroll
        for (int off = 1; off <= 2; off <<= 1) {
            mx0 = fmaxf(mx0, __shfl_xor_sync(0xffffffffu, mx0, off));
            mx1 = fmaxf(mx1, __shfl_xor_sync(0xffffffffu, mx1, off));
        }
        const float mn0 = fmaxf(m0, mx0), mn1 = fmaxf(m1, mx1);
        const float corr0 = __expf(m0 - mn0), corr1 = __expf(m1 - mn1);
        float sum0 = 0.f, sum1 = 0.f;
#pragma unroll
        for (int nt = 0; nt < 8; nt++) {
            s[nt].x = __expf(s[nt].x - mn0); sum0 += s[nt].x;
            s[nt].y = __expf(s[nt].y - mn0); sum0 += s[nt].y;
            s[nt].z = __expf(s[nt].z - mn1); sum1 += s[nt].z;
            s[nt].w = __expf(s[nt].w - mn1); sum1 += s[nt].w;
        }
#pragma unroll
        for (int off = 1; off <= 2; off <<= 1) {
            sum0 += __shfl_xor_sync(0xffffffffu, sum0, off);
            sum1 += __shfl_xor_sync(0xffffffffu, sum1, off);
        }
        l0 = l0 * corr0 + sum0; m0 = mn0;
        l1 = l1 * corr1 + sum1; m1 = mn1;
#pragma unroll
        for (int nt = 0; nt < 8; nt++) {
            o[nt].x *= corr0; o[nt].y *= corr0;
            o[nt].z *= corr1; o[nt].w *= corr1;
        }

        {
            const int pr0 = wid * 16 + g;
#pragma unroll
            for (int nt = 0; nt < 8; nt++) {
                Ps[pr0 * APAD + nt * 8 + 2 * r]       = totf32(s[nt].x);
                Ps[pr0 * APAD + nt * 8 + 2 * r + 1]   = totf32(s[nt].y);
                Ps[(pr0 + 8) * APAD + nt * 8 + 2 * r]     = totf32(s[nt].z);
                Ps[(pr0 + 8) * APAD + nt * 8 + 2 * r + 1] = totf32(s[nt].w);
            }
        }
        __syncwarp();
#pragma unroll
        for (int kk = 0; kk < 8; kk++) {
            const int pr0 = wid * 16 + g;
            uint32_t a0 = __float_as_uint(Ps[pr0 * APAD + kk * 8 + r]);
            uint32_t a1 = __float_as_uint(Ps[(pr0 + 8) * APAD + kk * 8 + r]);
            uint32_t a2 = __float_as_uint(Ps[pr0 * APAD + kk * 8 + r + 4]);
            uint32_t a3 = __float_as_uint(Ps[(pr0 + 8) * APAD + kk * 8 + r + 4]);
#pragma unroll
            for (int nt = 0; nt < 8; nt++) {
                uint32_t b0 = __float_as_uint(Vs[(kk * 8 + r) * APAD + nt * 8 + g]);
                uint32_t b1 = __float_as_uint(Vs[(kk * 8 + r + 4) * APAD + nt * 8 + g]);
                mma_tf32(o[nt], a0, a1, a2, a3, b0, b1);
            }
        }
        __syncwarp();
    }

    // store y pre-rounded (proj reads raw bits)
    const float inv0 = 1.0f / l0, inv1 = 1.0f / l1;
    const int b = bh >> 4, h = bh & 15;
#pragma unroll
    for (int nt = 0; nt < 8; nt++) {
        const int col = h * 64 + nt * 8 + 2 * r;
        float2 v0 = make_float2(totf32(o[nt].x * inv0), totf32(o[nt].y * inv0));
        float2 v1 = make_float2(totf32(o[nt].z * inv1), totf32(o[nt].w * inv1));
        *(float2*)&g_y[((size_t)b * Tt + row0g) * Cc + col] = v0;
        *(float2*)&g_y[((size_t)b * Tt + row1g) * Cc + col] = v1;
    }
}

// ---------------------------------------------------------------------------

extern "C" void kernel_launch(void* const* d_in, const int* in_sizes, int n_in,
                              void* d_out, int out_size)
{
    const float* x = (const float*)d_in[0];
    const float* w_qkv = (const float*)d_in[1];
    const float* b_qkv = (const float*)d_in[2];
    const float* w_proj = (const float*)d_in[3];
    const float* b_proj = (const float*)d_in[4];
    float* out = (float*)d_out;

    cudaFuncSetAttribute(gemm_tc<3 * Cc, true>,
                         cudaFuncAttributeMaxDynamicSharedMemorySize, GEMM_SMEM);
    cudaFuncSetAttribute(gemm_tc<Cc, false>,
                         cudaFuncAttributeMaxDynamicSharedMemorySize, GEMM_SMEM);
    cudaFuncSetAttribute(attn_tc,
                         cudaFuncAttributeMaxDynamicSharedMemorySize, ATTN_SMEM);

    // Pre-pass: rna-tf32 rounding copies
    round_x<<<(Bb * Tt * Cc / 4) / 256, 256>>>(x);          // x -> g_y
    round_wq<<<(Cc * 3 * Cc / 4) / 256, 256>>>(w_qkv);      // w_qkv -> g_wq
    round_wp<<<(Cc * Cc / 4) / 256, 256>>>(w_proj);         // w_proj -> g_wp

    // QKV GEMM: g_y(rounded x) x g_wq -> scatter rounded q/k/v
    gemm_tc<3 * Cc, true><<<dim3(24, 64), 256, GEMM_SMEM>>>(b_qkv, nullptr);
    // Flash attention: q/k/v -> g_y (rounded)
    attn_tc<<<dim3(Tt / 128, Bb * Hh), 256, ATTN_SMEM>>>();
    // Proj GEMM: g_y x g_wp + bias -> out (fp32)
    gemm_tc<Cc, false><<<dim3(8, 64), 256, GEMM_SMEM>>>(b_proj, out);
}

// round 12
// speedup vs baseline: 2.7965x; 1.0734x over previous
#include <cuda_runtime.h>
#include <math.h>
#include <stdint.h>

#define Bb 4
#define Tt 2048
#define Cc 1024
#define Hh 16
#define Dd 64

// Scratch (alloc-free rule: __device__ globals)
__device__ float g_q[(size_t)Bb*Hh*Tt*Dd];
__device__ float g_k[(size_t)Bb*Hh*Tt*Dd];
__device__ float g_v[(size_t)Bb*Hh*Tt*Dd];
__device__ float g_y[(size_t)Bb*Tt*Cc];      // rounded x, later rounded attn out
__device__ float g_wq[(size_t)Cc*3*Cc];      // rounded w_qkv
__device__ float g_wp[(size_t)Cc*Cc];        // rounded w_proj

__device__ __forceinline__ float totf32(float x) {
    uint32_t u;
    asm("cvt.rna.tf32.f32 %0, %1;" : "=r"(u) : "f"(x));
    return __uint_as_float(u);
}

__device__ __forceinline__ void mma_tf32(float4& c,
    uint32_t a0, uint32_t a1, uint32_t a2, uint32_t a3,
    uint32_t b0, uint32_t b1)
{
    asm volatile(
        "mma.sync.aligned.m16n8k8.row.col.f32.tf32.tf32.f32 "
        "{%0,%1,%2,%3}, {%4,%5,%6,%7}, {%8,%9}, {%0,%1,%2,%3};\n"
        : "+f"(c.x), "+f"(c.y), "+f"(c.z), "+f"(c.w)
        : "r"(a0), "r"(a1), "r"(a2), "r"(a3), "r"(b0), "r"(b1));
}

__device__ __forceinline__ void cp16(float* smem_dst, const float* gmem_src) {
    uint32_t s = (uint32_t)__cvta_generic_to_shared(smem_dst);
    asm volatile("cp.async.cg.shared.global [%0], [%1], 16;\n" :: "r"(s), "l"(gmem_src));
}
#define CP_COMMIT() asm volatile("cp.async.commit_group;\n" ::: "memory")
#define CP_WAIT(n)  asm volatile("cp.async.wait_group %0;\n" :: "n"(n) : "memory")

// ldmatrix x4 on 32-bit data -> tf32 a-fragment regs a0..a3.
__device__ __forceinline__ void ldsm_x4(uint32_t& r0, uint32_t& r1,
                                        uint32_t& r2, uint32_t& r3,
                                        const float* p)
{
    uint32_t a = (uint32_t)__cvta_generic_to_shared(p);
    asm volatile(
        "ldmatrix.sync.aligned.m8n8.x4.shared.b16 {%0,%1,%2,%3}, [%4];\n"
        : "=r"(r0), "=r"(r1), "=r"(r2), "=r"(r3) : "r"(a));
}

// ---------------------------------------------------------------------------
// Pre-pass: rna tf32 rounding copies.
// ---------------------------------------------------------------------------
__global__ void round_x(const float* __restrict__ in) {
    size_t i = (size_t)blockIdx.x * blockDim.x + threadIdx.x;
    float4 v = ((const float4*)in)[i];
    float4 t;
    t.x = totf32(v.x); t.y = totf32(v.y); t.z = totf32(v.z); t.w = totf32(v.w);
    ((float4*)g_y)[i] = t;
}
__global__ void round_wq(const float* __restrict__ in) {
    size_t i = (size_t)blockIdx.x * blockDim.x + threadIdx.x;
    float4 v = ((const float4*)in)[i];
    float4 t;
    t.x = totf32(v.x); t.y = totf32(v.y); t.z = totf32(v.z); t.w = totf32(v.w);
    ((float4*)g_wq)[i] = t;
}
__global__ void round_wp(const float* __restrict__ in) {
    size_t i = (size_t)blockIdx.x * blockDim.x + threadIdx.x;
    float4 v = ((const float4*)in)[i];
    float4 t;
    t.x = totf32(v.x); t.y = totf32(v.y); t.z = totf32(v.z); t.w = totf32(v.w);
    ((float4*)g_wp)[i] = t;
}

// ---------------------------------------------------------------------------
// TF32 GEMM, 3-stage cp.async pipeline, ONE __syncthreads per BK=32 tile.
// 128x128 CTA tile, 256 threads (8 warps 2x4), warp tile 64x32, 2 CTAs/SM.
// ---------------------------------------------------------------------------
#define ASTG (128 * 36)
#define BSTG (32 * 136)
#define GEMM_SMEM ((3 * ASTG + 3 * BSTG) * 4)  // 107520 B

template<int N, bool SCATTER>
__global__ __launch_bounds__(256, 2) void gemm_tc(
    const float* __restrict__ bias, float* __restrict__ Out)
{
    const int K = Cc;
    extern __shared__ float dsm[];
    float* Abuf = dsm;               // 3 x [128][36]
    float* Bbuf = dsm + 3 * ASTG;    // 3 x [32][136]

    const int tid = threadIdx.x;
    const int wid = tid >> 5, lane = tid & 31;
    const int warp_m = wid >> 2, warp_n = wid & 3;
    const int g = lane >> 2, r = lane & 3;

    const int mBlk = blockIdx.y * 128, nBlk = blockIdx.x * 128;
    const float* Abase = g_y;
    const float* W = SCATTER ? g_wq : g_wp;

    const int am = tid >> 1, ac = (tid & 1) * 16;
    const int bk = tid >> 3, bn = (tid & 7) * 16;
    const float* aptr = Abase + (size_t)(mBlk + am) * K + ac;
    const float* wptr = W + (size_t)bk * N + nBlk + bn;

    const int NT = K / 32;  // 32
    const int lrow = lane & 15, lkh = (lane >> 4) * 4;

#define ISSUE_TILE(kt, stg)                                                  \
    do {                                                                     \
        float* ad = Abuf + (stg) * ASTG + am * 36 + ac;                      \
        const float* as = aptr + (kt) * 32;                                  \
        _Pragma("unroll")                                                    \
        for (int i = 0; i < 4; i++) cp16(ad + i * 4, as + i * 4);            \
        float* bd = Bbuf + (stg) * BSTG + bk * 136 + bn;                     \
        const float* bs = wptr + (size_t)(kt) * 32 * N;                      \
        _Pragma("unroll")                                                    \
        for (int i = 0; i < 4; i++) cp16(bd + i * 4, bs + i * 4);            \
    } while (0)

    ISSUE_TILE(0, 0); CP_COMMIT();
    ISSUE_TILE(1, 1); CP_COMMIT();

    float4 acc[4][4];
#pragma unroll
    for (int i = 0; i < 4; i++)
#pragma unroll
        for (int j = 0; j < 4; j++) acc[i][j] = make_float4(0.f, 0.f, 0.f, 0.f);

    for (int kt = 0; kt < NT; kt++) {
        // stage kt must be resident; stage kt+1 may still be in flight
        if (kt < NT - 1) { CP_WAIT(1); } else { CP_WAIT(0); }
        __syncthreads();  // also guards overwrite of stage (kt+2)%3 = (kt-1)%3
        if (kt + 2 < NT) { ISSUE_TILE(kt + 2, (kt + 2) % 3); CP_COMMIT(); }

        const float* As = Abuf + (kt % 3) * ASTG;
        const float* Bs = Bbuf + (kt % 3) * BSTG;

#pragma unroll
        for (int kk = 0; kk < 4; kk++) {
            const int k = kk * 8;
            uint32_t af[4][4], bf[4][2];
#pragma unroll
            for (int mt = 0; mt < 4; mt++) {
                const float* p = As + (warp_m * 64 + mt * 16 + lrow) * 36 + k + lkh;
                ldsm_x4(af[mt][0], af[mt][1], af[mt][2], af[mt][3], p);
            }
#pragma unroll
            for (int nt = 0; nt < 4; nt++) {
                const int n0 = warp_n * 32 + nt * 8 + g;
                bf[nt][0] = __float_as_uint(Bs[(k + r) * 136 + n0]);
                bf[nt][1] = __float_as_uint(Bs[(k + r + 4) * 136 + n0]);
            }
#pragma unroll
            for (int mt = 0; mt < 4; mt++)
#pragma unroll
                for (int nt = 0; nt < 4; nt++)
                    mma_tf32(acc[mt][nt],
                             af[mt][0], af[mt][1], af[mt][2], af[mt][3],
                             bf[nt][0], bf[nt][1]);
        }
    }
#undef ISSUE_TILE

    // Epilogue (SCATTER stores pre-rounded tf32 for the attention MMAs)
#pragma unroll
    for (int mt = 0; mt < 4; mt++) {
        const int mA = mBlk + warp_m * 64 + mt * 16 + g;
        const int mB = mA + 8;
#pragma unroll
        for (int nt = 0; nt < 4; nt++) {
            const int n = nBlk + warp_n * 32 + nt * 8 + 2 * r;
            const float b0 = bias[n], b1 = bias[n + 1];
            if (SCATTER) {
                float2 v0 = make_float2(totf32(acc[mt][nt].x + b0), totf32(acc[mt][nt].y + b1));
                float2 v1 = make_float2(totf32(acc[mt][nt].z + b0), totf32(acc[mt][nt].w + b1));
                const int which = n >> 10;
                const int h = (n & 1023) >> 6;
                const int d = n & 63;
                float* outp = (which == 0) ? g_q : ((which == 1) ? g_k : g_v);
                {
                    const int b_ = mA >> 11, t_ = mA & 2047;
                    *(float2*)&outp[(((size_t)(b_ * Hh + h)) * Tt + t_) * Dd + d] = v0;
                }
                {
                    const int b_ = mB >> 11, t_ = mB & 2047;
                    *(float2*)&outp[(((size_t)(b_ * Hh + h)) * Tt + t_) * Dd + d] = v1;
                }
            } else {
                float2 v0 = make_float2(acc[mt][nt].x + b0, acc[mt][nt].y + b1);
                float2 v1 = make_float2(acc[mt][nt].z + b0, acc[mt][nt].w + b1);
                *(float2*)&Out[(size_t)mA * N + n] = v0;
                *(float2*)&Out[(size_t)mB * N + n] = v1;
            }
        }
    }
}

// ---------------------------------------------------------------------------
// Flash attention (causal), TF32 MMA, 3-stage cp.async K/V pipeline,
// ONE __syncthreads per kv-block iteration.
// ---------------------------------------------------------------------------
#define APAD 72
#define KVSTG (2 * 64 * APAD)                      // K + V per stage (floats)
#define ATTN_SMEM ((3 * KVSTG + 128 * APAD) * 4)   // 147456 B

__global__ __launch_bounds__(256, 1) void attn_tc()
{
    extern __shared__ float sm[];
    float* Ps = sm + 3 * KVSTG;   // [128][72] (also Q staging)

    const int tid = threadIdx.x;
    const int wid = tid >> 5, lane = tid & 31;
    const int g = lane >> 2, r = lane & 3;
    const int bh = blockIdx.y;
    const int qt = gridDim.x - 1 - blockIdx.x;

    const float* Qg = g_q + (size_t)bh * Tt * Dd;
    const float* Kg = g_k + (size_t)bh * Tt * Dd;
    const float* Vg = g_v + (size_t)bh * Tt * Dd;

    const int ktmax = 2 * qt + 1;  // >= 1 always

    // cp.async staging coords for K/V
    const int krow = tid >> 2, kcol = (tid & 3) * 16;

#define ISSUE_KV(kt, stg)                                                    \
    do {                                                                     \
        float* kd = sm + (stg) * KVSTG + krow * APAD + kcol;                 \
        float* vd = kd + 64 * APAD;                                          \
        const float* ks_ = Kg + ((size_t)(kt) * 64 + krow) * Dd + kcol;      \
        const float* vs_ = Vg + ((size_t)(kt) * 64 + krow) * Dd + kcol;      \
        _Pragma("unroll")                                                    \
        for (int i = 0; i < 4; i++) cp16(kd + i * 4, ks_ + i * 4);           \
        _Pragma("unroll")                                                    \
        for (int i = 0; i < 4; i++) cp16(vd + i * 4, vs_ + i * 4);           \
    } while (0)

    ISSUE_KV(0, 0); CP_COMMIT();
    ISSUE_KV(1, 1); CP_COMMIT();

    // Stage Q tile [128][64] into Ps, then fragments to registers
    {
        const int qr = tid >> 1, qc = (tid & 1) * 32;
        const float* qsrc = Qg + ((size_t)qt * 128 + qr) * Dd + qc;
#pragma unroll
        for (int i = 0; i < 8; i++)
            *(float4*)&Ps[qr * APAD + qc + i * 4] = *(const float4*)(qsrc + i * 4);
    }
    __syncthreads();

    uint32_t qf[8][4];  // pre-rounded, *0.125f exact on tf32
    {
        const int row0 = wid * 16 + g;
#pragma unroll
        for (int kd = 0; kd < 8; kd++) {
            qf[kd][0] = __float_as_uint(Ps[row0 * APAD + kd * 8 + r] * 0.125f);
            qf[kd][1] = __float_as_uint(Ps[(row0 + 8) * APAD + kd * 8 + r] * 0.125f);
            qf[kd][2] = __float_as_uint(Ps[row0 * APAD + kd * 8 + r + 4] * 0.125f);
            qf[kd][3] = __float_as_uint(Ps[(row0 + 8) * APAD + kd * 8 + r + 4] * 0.125f);
        }
    }
    __syncthreads();  // everyone done reading Q from Ps before P writes

    float m0 = -1e30f, m1 = -1e30f, l0 = 0.f, l1 = 0.f;
    float4 o[8];
#pragma unroll
    for (int i = 0; i < 8; i++) o[i] = make_float4(0.f, 0.f, 0.f, 0.f);

    const int row0g = qt * 128 + wid * 16 + g;
    const int row1g = row0g + 8;

    for (int kt = 0; kt <= ktmax; kt++) {
        if (kt < ktmax) { CP_WAIT(1); } else { CP_WAIT(0); }
        __syncthreads();  // stage kt ready; guards overwrite of (kt+2)%3=(kt-1)%3
        if (kt + 2 <= ktmax) { ISSUE_KV(kt + 2, (kt + 2) % 3); CP_COMMIT(); }

        const float* Ks = sm + (kt % 3) * KVSTG;
        const float* Vs = Ks + 64 * APAD;

        // ---- S = (Q*scale) K^T
        float4 s[8];
#pragma unroll
        for (int nt = 0; nt < 8; nt++) s[nt] = make_float4(0.f, 0.f, 0.f, 0.f);
#pragma unroll
        for (int kd = 0; kd < 8; kd++) {
#pragma unroll
            for (int nt = 0; nt < 8; nt++) {
                uint32_t b0 = __float_as_uint(Ks[(nt * 8 + g) * APAD + kd * 8 + r]);
                uint32_t b1 = __float_as_uint(Ks[(nt * 8 + g) * APAD + kd * 8 + r + 4]);
                mma_tf32(s[nt], qf[kd][0], qf[kd][1], qf[kd][2], qf[kd][3], b0, b1);
            }
        }

        if (kt * 64 + 63 > qt * 128 + wid * 16) {
#pragma unroll
            for (int nt = 0; nt < 8; nt++) {
                const int c0 = kt * 64 + nt * 8 + 2 * r, c1 = c0 + 1;
                if (c0 > row0g) s[nt].x = -1e30f;
                if (c1 > row0g) s[nt].y = -1e30f;
                if (c0 > row1g) s[nt].z = -1e30f;
                if (c1 > row1g) s[nt].w = -1e30f;
            }
        }

        // ---- online softmax
        float mx0 = -1e30f, mx1 = -1e30f;
#pragma unroll
        for (int nt = 0; nt < 8; nt++) {
            mx0 = fmaxf(mx0, fmaxf(s[nt].x, s[nt].y));
            mx1 = fmaxf(mx1, fmaxf(s[nt].z, s[nt].w));
        }
#pragma unroll
        for (int off = 1; off <= 2; off <<= 1) {
            mx0 = fmaxf(mx0, __shfl_xor_sync(0xffffffffu, mx0, off));
            mx1 = fmaxf(mx1, __shfl_xor_sync(0xffffffffu, mx1, off));
        }
        const float mn0 = fmaxf(m0, mx0), mn1 = fmaxf(m1, mx1);
        const float corr0 = __expf(m0 - mn0), corr1 = __expf(m1 - mn1);
        float sum0 = 0.f, sum1 = 0.f;
#pragma unroll
        for (int nt = 0; nt < 8; nt++) {
            s[nt].x = __expf(s[nt].x - mn0); sum0 += s[nt].x;
            s[nt].y = __expf(s[nt].y - mn0); sum0 += s[nt].y;
            s[nt].z = __expf(s[nt].z - mn1); sum1 += s[nt].z;
            s[nt].w = __expf(s[nt].w - mn1); sum1 += s[nt].w;
        }
#pragma unroll
        for (int off = 1; off <= 2; off <<= 1) {
            sum0 += __shfl_xor_sync(0xffffffffu, sum0, off);
            sum1 += __shfl_xor_sync(0xffffffffu, sum1, off);
        }
        l0 = l0 * corr0 + sum0; m0 = mn0;
        l1 = l1 * corr1 + sum1; m1 = mn1;
#pragma unroll
        for (int nt = 0; nt < 8; nt++) {
            o[nt].x *= corr0; o[nt].y *= corr0;
            o[nt].z *= corr1; o[nt].w *= corr1;
        }

        // ---- P -> warp-private Ps rows (tf32), PV MMAs
        {
            const int pr0 = wid * 16 + g;
#pragma unroll
            for (int nt = 0; nt < 8; nt++) {
                Ps[pr0 * APAD + nt * 8 + 2 * r]       = totf32(s[nt].x);
                Ps[pr0 * APAD + nt * 8 + 2 * r + 1]   = totf32(s[nt].y);
                Ps[(pr0 + 8) * APAD + nt * 8 + 2 * r]     = totf32(s[nt].z);
                Ps[(pr0 + 8) * APAD + nt * 8 + 2 * r + 1] = totf32(s[nt].w);
            }
        }
        __syncwarp();
#pragma unroll
        for (int kk = 0; kk < 8; kk++) {
            const int pr0 = wid * 16 + g;
            uint32_t a0 = __float_as_uint(Ps[pr0 * APAD + kk * 8 + r]);
            uint32_t a1 = __float_as_uint(Ps[(pr0 + 8) * APAD + kk * 8 + r]);
            uint32_t a2 = __float_as_uint(Ps[pr0 * APAD + kk * 8 + r + 4]);
            uint32_t a3 = __float_as_uint(Ps[(pr0 + 8) * APAD + kk * 8 + r + 4]);
#pragma unroll
            for (int nt = 0; nt < 8; nt++) {
                uint32_t b0 = __float_as_uint(Vs[(kk * 8 + r) * APAD + nt * 8 + g]);
                uint32_t b1 = __float_as_uint(Vs[(kk * 8 + r + 4) * APAD + nt * 8 + g]);
                mma_tf32(o[nt], a0, a1, a2, a3, b0, b1);
            }
        }
        __syncwarp();
    }
#undef ISSUE_KV

    // store y pre-rounded (proj reads raw bits)
    const float inv0 = 1.0f / l0, inv1 = 1.0f / l1;
    const int b = bh >> 4, h = bh & 15;
#pragma unroll
    for (int nt = 0; nt < 8; nt++) {
        const int col = h * 64 + nt * 8 + 2 * r;
        float2 v0 = make_float2(totf32(o[nt].x * inv0), totf32(o[nt].y * inv0));
        float2 v1 = make_float2(totf32(o[nt].z * inv1), totf32(o[nt].w * inv1));
        *(float2*)&g_y[((size_t)b * Tt + row0g) * Cc + col] = v0;
        *(float2*)&g_y[((size_t)b * Tt + row1g) * Cc + col] = v1;
    }
}

// ---------------------------------------------------------------------------

extern "C" void kernel_launch(void* const* d_in, const int* in_sizes, int n_in,
                              void* d_out, int out_size)
{
    const float* x = (const float*)d_in[0];
    const float* w_qkv = (const float*)d_in[1];
    const float* b_qkv = (const float*)d_in[2];
    const float* w_proj = (const float*)d_in[3];
    const float* b_proj = (const float*)d_in[4];
    float* out = (float*)d_out;

    cudaFuncSetAttribute(gemm_tc<3 * Cc, true>,
                         cudaFuncAttributeMaxDynamicSharedMemorySize, GEMM_SMEM);
    cudaFuncSetAttribute(gemm_tc<Cc, false>,
                         cudaFuncAttributeMaxDynamicSharedMemorySize, GEMM_SMEM);
    cudaFuncSetAttribute(attn_tc,
                         cudaFuncAttributeMaxDynamicSharedMemorySize, ATTN_SMEM);

    // Pre-pass: rna-tf32 rounding copies
    round_x<<<(Bb * Tt * Cc / 4) / 256, 256>>>(x);
    round_wq<<<(Cc * 3 * Cc / 4) / 256, 256>>>(w_qkv);
    round_wp<<<(Cc * Cc / 4) / 256, 256>>>(w_proj);

    // QKV GEMM: g_y(rounded x) x g_wq -> scatter rounded q/k/v
    gemm_tc<3 * Cc, true><<<dim3(24, 64), 256, GEMM_SMEM>>>(b_qkv, nullptr);
    // Flash attention: q/k/v -> g_y (rounded)
    attn_tc<<<dim3(Tt / 128, Bb * Hh), 256, ATTN_SMEM>>>();
    // Proj GEMM: g_y x g_wp + bias -> out (fp32)
    gemm_tc<Cc, false><<<dim3(8, 64), 256, GEMM_SMEM>>>(b_proj, out);
}

// round 14
// speedup vs baseline: 2.8304x; 1.0121x over previous
#include <cuda_runtime.h>
#include <math.h>
#include <stdint.h>

#define Bb 4
#define Tt 2048
#define Cc 1024
#define Hh 16
#define Dd 64

// Scratch (alloc-free rule: __device__ globals)
__device__ float g_q[(size_t)Bb*Hh*Tt*Dd];
__device__ float g_k[(size_t)Bb*Hh*Tt*Dd];
__device__ float g_v[(size_t)Bb*Hh*Tt*Dd];
__device__ float g_y[(size_t)Bb*Tt*Cc];      // rounded x, later rounded attn out
__device__ float g_wq[(size_t)Cc*3*Cc];      // rounded w_qkv
__device__ float g_wp[(size_t)Cc*Cc];        // rounded w_proj

__device__ __forceinline__ float totf32(float x) {
    uint32_t u;
    asm("cvt.rna.tf32.f32 %0, %1;" : "=r"(u) : "f"(x));
    return __uint_as_float(u);
}

__device__ __forceinline__ void mma_tf32(float4& c,
    uint32_t a0, uint32_t a1, uint32_t a2, uint32_t a3,
    uint32_t b0, uint32_t b1)
{
    asm volatile(
        "mma.sync.aligned.m16n8k8.row.col.f32.tf32.tf32.f32 "
        "{%0,%1,%2,%3}, {%4,%5,%6,%7}, {%8,%9}, {%0,%1,%2,%3};\n"
        : "+f"(c.x), "+f"(c.y), "+f"(c.z), "+f"(c.w)
        : "r"(a0), "r"(a1), "r"(a2), "r"(a3), "r"(b0), "r"(b1));
}

__device__ __forceinline__ void cp16(float* smem_dst, const float* gmem_src) {
    uint32_t s = (uint32_t)__cvta_generic_to_shared(smem_dst);
    asm volatile("cp.async.cg.shared.global [%0], [%1], 16;\n" :: "r"(s), "l"(gmem_src));
}
#define CP_COMMIT() asm volatile("cp.async.commit_group;\n" ::: "memory")
#define CP_WAIT(n)  asm volatile("cp.async.wait_group %0;\n" :: "n"(n) : "memory")

// ldmatrix x4 on 32-bit data -> tf32 a-fragment regs a0..a3.
__device__ __forceinline__ void ldsm_x4(uint32_t& r0, uint32_t& r1,
                                        uint32_t& r2, uint32_t& r3,
                                        const float* p)
{
    uint32_t a = (uint32_t)__cvta_generic_to_shared(p);
    asm volatile(
        "ldmatrix.sync.aligned.m8n8.x4.shared.b16 {%0,%1,%2,%3}, [%4];\n"
        : "=r"(r0), "=r"(r1), "=r"(r2), "=r"(r3) : "r"(a));
}

// ---------------------------------------------------------------------------
// Pre-pass: rna tf32 rounding copies.
// ---------------------------------------------------------------------------
__global__ void round_x(const float* __restrict__ in) {
    size_t i = (size_t)blockIdx.x * blockDim.x + threadIdx.x;
    float4 v = ((const float4*)in)[i];
    float4 t;
    t.x = totf32(v.x); t.y = totf32(v.y); t.z = totf32(v.z); t.w = totf32(v.w);
    ((float4*)g_y)[i] = t;
}
__global__ void round_wq(const float* __restrict__ in) {
    size_t i = (size_t)blockIdx.x * blockDim.x + threadIdx.x;
    float4 v = ((const float4*)in)[i];
    float4 t;
    t.x = totf32(v.x); t.y = totf32(v.y); t.z = totf32(v.z); t.w = totf32(v.w);
    ((float4*)g_wq)[i] = t;
}
__global__ void round_wp(const float* __restrict__ in) {
    size_t i = (size_t)blockIdx.x * blockDim.x + threadIdx.x;
    float4 v = ((const float4*)in)[i];
    float4 t;
    t.x = totf32(v.x); t.y = totf32(v.y); t.z = totf32(v.z); t.w = totf32(v.w);
    ((float4*)g_wp)[i] = t;
}

// ---------------------------------------------------------------------------
// TF32 GEMM, 3-stage cp.async pipeline, ONE __syncthreads per BK=32 tile.
// 128x128 CTA tile, 256 threads (8 warps 2x4), warp tile 64x32, 2 CTAs/SM.
// (unchanged from R12)
// ---------------------------------------------------------------------------
#define ASTG (128 * 36)
#define BSTG (32 * 136)
#define GEMM_SMEM ((3 * ASTG + 3 * BSTG) * 4)  // 107520 B

template<int N, bool SCATTER>
__global__ __launch_bounds__(256, 2) void gemm_tc(
    const float* __restrict__ bias, float* __restrict__ Out)
{
    const int K = Cc;
    extern __shared__ float dsm[];
    float* Abuf = dsm;
    float* Bbuf = dsm + 3 * ASTG;

    const int tid = threadIdx.x;
    const int wid = tid >> 5, lane = tid & 31;
    const int warp_m = wid >> 2, warp_n = wid & 3;
    const int g = lane >> 2, r = lane & 3;

    const int mBlk = blockIdx.y * 128, nBlk = blockIdx.x * 128;
    const float* W = SCATTER ? g_wq : g_wp;

    const int am = tid >> 1, ac = (tid & 1) * 16;
    const int bk = tid >> 3, bn = (tid & 7) * 16;
    const float* aptr = g_y + (size_t)(mBlk + am) * K + ac;
    const float* wptr = W + (size_t)bk * N + nBlk + bn;

    const int NT = K / 32;
    const int lrow = lane & 15, lkh = (lane >> 4) * 4;

#define ISSUE_TILE(kt, stg)                                                  \
    do {                                                                     \
        float* ad = Abuf + (stg) * ASTG + am * 36 + ac;                      \
        const float* as = aptr + (kt) * 32;                                  \
        _Pragma("unroll")                                                    \
        for (int i = 0; i < 4; i++) cp16(ad + i * 4, as + i * 4);            \
        float* bd = Bbuf + (stg) * BSTG + bk * 136 + bn;                     \
        const float* bs = wptr + (size_t)(kt) * 32 * N;                      \
        _Pragma("unroll")                                                    \
        for (int i = 0; i < 4; i++) cp16(bd + i * 4, bs + i * 4);            \
    } while (0)

    ISSUE_TILE(0, 0); CP_COMMIT();
    ISSUE_TILE(1, 1); CP_COMMIT();

    float4 acc[4][4];
#pragma unroll
    for (int i = 0; i < 4; i++)
#pragma unroll
        for (int j = 0; j < 4; j++) acc[i][j] = make_float4(0.f, 0.f, 0.f, 0.f);

    for (int kt = 0; kt < NT; kt++) {
        if (kt < NT - 1) { CP_WAIT(1); } else { CP_WAIT(0); }
        __syncthreads();
        if (kt + 2 < NT) { ISSUE_TILE(kt + 2, (kt + 2) % 3); CP_COMMIT(); }

        const float* As = Abuf + (kt % 3) * ASTG;
        const float* Bs = Bbuf + (kt % 3) * BSTG;

#pragma unroll
        for (int kk = 0; kk < 4; kk++) {
            const int k = kk * 8;
            uint32_t af[4][4], bf[4][2];
#pragma unroll
            for (int mt = 0; mt < 4; mt++) {
                const float* p = As + (warp_m * 64 + mt * 16 + lrow) * 36 + k + lkh;
                ldsm_x4(af[mt][0], af[mt][1], af[mt][2], af[mt][3], p);
            }
#pragma unroll
            for (int nt = 0; nt < 4; nt++) {
                const int n0 = warp_n * 32 + nt * 8 + g;
                bf[nt][0] = __float_as_uint(Bs[(k + r) * 136 + n0]);
                bf[nt][1] = __float_as_uint(Bs[(k + r + 4) * 136 + n0]);
            }
#pragma unroll
            for (int mt = 0; mt < 4; mt++)
#pragma unroll
                for (int nt = 0; nt < 4; nt++)
                    mma_tf32(acc[mt][nt],
                             af[mt][0], af[mt][1], af[mt][2], af[mt][3],
                             bf[nt][0], bf[nt][1]);
        }
    }
#undef ISSUE_TILE

#pragma unroll
    for (int mt = 0; mt < 4; mt++) {
        const int mA = mBlk + warp_m * 64 + mt * 16 + g;
        const int mB = mA + 8;
#pragma unroll
        for (int nt = 0; nt < 4; nt++) {
            const int n = nBlk + warp_n * 32 + nt * 8 + 2 * r;
            const float b0 = bias[n], b1 = bias[n + 1];
            if (SCATTER) {
                float2 v0 = make_float2(totf32(acc[mt][nt].x + b0), totf32(acc[mt][nt].y + b1));
                float2 v1 = make_float2(totf32(acc[mt][nt].z + b0), totf32(acc[mt][nt].w + b1));
                const int which = n >> 10;
                const int h = (n & 1023) >> 6;
                const int d = n & 63;
                float* outp = (which == 0) ? g_q : ((which == 1) ? g_k : g_v);
                {
                    const int b_ = mA >> 11, t_ = mA & 2047;
                    *(float2*)&outp[(((size_t)(b_ * Hh + h)) * Tt + t_) * Dd + d] = v0;
                }
                {
                    const int b_ = mB >> 11, t_ = mB & 2047;
                    *(float2*)&outp[(((size_t)(b_ * Hh + h)) * Tt + t_) * Dd + d] = v1;
                }
            } else {
                float2 v0 = make_float2(acc[mt][nt].x + b0, acc[mt][nt].y + b1);
                float2 v1 = make_float2(acc[mt][nt].z + b0, acc[mt][nt].w + b1);
                *(float2*)&Out[(size_t)mA * N + n] = v0;
                *(float2*)&Out[(size_t)mB * N + n] = v1;
            }
        }
    }
}

// ---------------------------------------------------------------------------
// Flash attention (causal), TF32 MMA, 2-stage cp.async K/V pipeline so TWO
// CTAs fit per SM (108 KB smem each). Two __syncthreads per kv-iteration;
// barrier stalls of one CTA overlap the other CTA's compute.
// ---------------------------------------------------------------------------
#define APAD 72
#define KVSTG (2 * 64 * APAD)                      // K + V per stage (floats)
#define ATTN_SMEM ((2 * KVSTG + 128 * APAD) * 4)   // 110592 B

__global__ __launch_bounds__(256, 2) void attn_tc()
{
    extern __shared__ float sm[];
    float* Ps = sm + 2 * KVSTG;   // [128][72] (also Q staging)

    const int tid = threadIdx.x;
    const int wid = tid >> 5, lane = tid & 31;
    const int g = lane >> 2, r = lane & 3;
    const int bh = blockIdx.y;
    const int qt = gridDim.x - 1 - blockIdx.x;  // heavy tiles first

    const float* Qg = g_q + (size_t)bh * Tt * Dd;
    const float* Kg = g_k + (size_t)bh * Tt * Dd;
    const float* Vg = g_v + (size_t)bh * Tt * Dd;

    const int ktmax = 2 * qt + 1;  // >= 1 always
    const int krow = tid >> 2, kcol = (tid & 3) * 16;

#define ISSUE_KV(kt, stg)                                                    \
    do {                                                                     \
        float* kd = sm + (stg) * KVSTG + krow * APAD + kcol;                 \
        float* vd = kd + 64 * APAD;                                          \
        const float* ks_ = Kg + ((size_t)(kt) * 64 + krow) * Dd + kcol;      \
        const float* vs_ = Vg + ((size_t)(kt) * 64 + krow) * Dd + kcol;      \
        _Pragma("unroll")                                                    \
        for (int i = 0; i < 4; i++) cp16(kd + i * 4, ks_ + i * 4);           \
        _Pragma("unroll")                                                    \
        for (int i = 0; i < 4; i++) cp16(vd + i * 4, vs_ + i * 4);           \
    } while (0)

    ISSUE_KV(0, 0); CP_COMMIT();
    ISSUE_KV(1, 1); CP_COMMIT();

    // Stage Q tile [128][64] into Ps, then fragments to registers
    {
        const int qr = tid >> 1, qc = (tid & 1) * 32;
        const float* qsrc = Qg + ((size_t)qt * 128 + qr) * Dd + qc;
#pragma unroll
        for (int i = 0; i < 8; i++)
            *(float4*)&Ps[qr * APAD + qc + i * 4] = *(const float4*)(qsrc + i * 4);
    }
    __syncthreads();

    uint32_t qf[8][4];  // pre-rounded, *0.125f exact on tf32
    {
        const int row0 = wid * 16 + g;
#pragma unroll
        for (int kd = 0; kd < 8; kd++) {
            qf[kd][0] = __float_as_uint(Ps[row0 * APAD + kd * 8 + r] * 0.125f);
            qf[kd][1] = __float_as_uint(Ps[(row0 + 8) * APAD + kd * 8 + r] * 0.125f);
            qf[kd][2] = __float_as_uint(Ps[row0 * APAD + kd * 8 + r + 4] * 0.125f);
            qf[kd][3] = __float_as_uint(Ps[(row0 + 8) * APAD + kd * 8 + r + 4] * 0.125f);
        }
    }
    __syncthreads();  // Q reads done before P writes

    float m0 = -1e30f, m1 = -1e30f, l0 = 0.f, l1 = 0.f;
    float4 o[8];
#pragma unroll
    for (int i = 0; i < 8; i++) o[i] = make_float4(0.f, 0.f, 0.f, 0.f);

    const int row0g = qt * 128 + wid * 16 + g;
    const int row1g = row0g + 8;

    for (int kt = 0; kt <= ktmax; kt++) {
        if (kt < ktmax) { CP_WAIT(1); } else { CP_WAIT(0); }
        __syncthreads();  // stage kt visible to all threads

        const float* Ks = sm + (kt & 1) * KVSTG;
        const float* Vs = Ks + 64 * APAD;

        // ---- S = (Q*scale) K^T
        float4 s[8];
#pragma unroll
        for (int nt = 0; nt < 8; nt++) s[nt] = make_float4(0.f, 0.f, 0.f, 0.f);
#pragma unroll
        for (int kd = 0; kd < 8; kd++) {
#pragma unroll
            for (int nt = 0; nt < 8; nt++) {
                uint32_t b0 = __float_as_uint(Ks[(nt * 8 + g) * APAD + kd * 8 + r]);
                uint32_t b1 = __float_as_uint(Ks[(nt * 8 + g) * APAD + kd * 8 + r + 4]);
                mma_tf32(s[nt], qf[kd][0], qf[kd][1], qf[kd][2], qf[kd][3], b0, b1);
            }
        }

        if (kt * 64 + 63 > qt * 128 + wid * 16) {
#pragma unroll
            for (int nt = 0; nt < 8; nt++) {
                const int c0 = kt * 64 + nt * 8 + 2 * r, c1 = c0 + 1;
                if (c0 > row0g) s[nt].x = -1e30f;
                if (c1 > row0g) s[nt].y = -1e30f;
                if (c0 > row1g) s[nt].z = -1e30f;
                if (c1 > row1g) s[nt].w = -1e30f;
            }
        }

        // ---- online softmax
        float mx0 = -1e30f, mx1 = -1e30f;
#pragma unroll
        for (int nt = 0; nt < 8; nt++) {
            mx0 = fmaxf(mx0, fmaxf(s[nt].x, s[nt].y));
            mx1 = fmaxf(mx1, fmaxf(s[nt].z, s[nt].w));
        }
#pragma unroll
        for (int off = 1; off <= 2; off <<= 1) {
            mx0 = fmaxf(mx0, __shfl_xor_sync(0xffffffffu, mx0, off));
            mx1 = fmaxf(mx1, __shfl_xor_sync(0xffffffffu, mx1, off));
        }
        const float mn0 = fmaxf(m0, mx0), mn1 = fmaxf(m1, mx1);
        const float corr0 = __expf(m0 - mn0), corr1 = __expf(m1 - mn1);
        float sum0 = 0.f, sum1 = 0.f;
#pragma unroll
        for (int nt = 0; nt < 8; nt++) {
            s[nt].x = __expf(s[nt].x - mn0); sum0 += s[nt].x;
            s[nt].y = __expf(s[nt].y - mn0); sum0 += s[nt].y;
            s[nt].z = __expf(s[nt].z - mn1); sum1 += s[nt].z;
            s[nt].w = __expf(s[nt].w - mn1); sum1 += s[nt].w;
        }
#pragma unroll
        for (int off = 1; off <= 2; off <<= 1) {
            sum0 += __shfl_xor_sync(0xffffffffu, sum0, off);
            sum1 += __shfl_xor_sync(0xffffffffu, sum1, off);
        }
        l0 = l0 * corr0 + sum0; m0 = mn0;
        l1 = l1 * corr1 + sum1; m1 = mn1;
#pragma unroll
        for (int nt = 0; nt < 8; nt++) {
            o[nt].x *= corr0; o[nt].y *= corr0;
            o[nt].z *= corr1; o[nt].w *= corr1;
        }

        // ---- P -> warp-private Ps rows (tf32), PV MMAs
        {
            const int pr0 = wid * 16 + g;
#pragma unroll
            for (int nt = 0; nt < 8; nt++) {
                Ps[pr0 * APAD + nt * 8 + 2 * r]       = totf32(s[nt].x);
                Ps[pr0 * APAD + nt * 8 + 2 * r + 1]   = totf32(s[nt].y);
                Ps[(pr0 + 8) * APAD + nt * 8 + 2 * r]     = totf32(s[nt].z);
                Ps[(pr0 + 8) * APAD + nt * 8 + 2 * r + 1] = totf32(s[nt].w);
            }
        }
        __syncwarp();
#pragma unroll
        for (int kk = 0; kk < 8; kk++) {
            const int pr0 = wid * 16 + g;
            uint32_t a0 = __float_as_uint(Ps[pr0 * APAD + kk * 8 + r]);
            uint32_t a1 = __float_as_uint(Ps[(pr0 + 8) * APAD + kk * 8 + r]);
            uint32_t a2 = __float_as_uint(Ps[pr0 * APAD + kk * 8 + r + 4]);
            uint32_t a3 = __float_as_uint(Ps[(pr0 + 8) * APAD + kk * 8 + r + 4]);
#pragma unroll
            for (int nt = 0; nt < 8; nt++) {
                uint32_t b0 = __float_as_uint(Vs[(kk * 8 + r) * APAD + nt * 8 + g]);
                uint32_t b1 = __float_as_uint(Vs[(kk * 8 + r + 4) * APAD + nt * 8 + g]);
                mma_tf32(o[nt], a0, a1, a2, a3, b0, b1);
            }
        }

        __syncthreads();  // all warps done reading stage kt (K and V)
        if (kt + 2 <= ktmax) { ISSUE_KV(kt + 2, kt & 1); CP_COMMIT(); }
    }
#undef ISSUE_KV

    // store y pre-rounded (proj reads raw bits)
    const float inv0 = 1.0f / l0, inv1 = 1.0f / l1;
    const int b = bh >> 4, h = bh & 15;
#pragma unroll
    for (int nt = 0; nt < 8; nt++) {
        const int col = h * 64 + nt * 8 + 2 * r;
        float2 v0 = make_float2(totf32(o[nt].x * inv0), totf32(o[nt].y * inv0));
        float2 v1 = make_float2(totf32(o[nt].z * inv1), totf32(o[nt].w * inv1));
        *(float2*)&g_y[((size_t)b * Tt + row0g) * Cc + col] = v0;
        *(float2*)&g_y[((size_t)b * Tt + row1g) * Cc + col] = v1;
    }
}

// ---------------------------------------------------------------------------

extern "C" void kernel_launch(void* const* d_in, const int* in_sizes, int n_in,
                              void* d_out, int out_size)
{
    const float* x = (const float*)d_in[0];
    const float* w_qkv = (const float*)d_in[1];
    const float* b_qkv = (const float*)d_in[2];
    const float* w_proj = (const float*)d_in[3];
    const float* b_proj = (const float*)d_in[4];
    float* out = (float*)d_out;

    cudaFuncSetAttribute(gemm_tc<3 * Cc, true>,
                         cudaFuncAttributeMaxDynamicSharedMemorySize, GEMM_SMEM);
    cudaFuncSetAttribute(gemm_tc<Cc, false>,
                         cudaFuncAttributeMaxDynamicSharedMemorySize, GEMM_SMEM);
    cudaFuncSetAttribute(attn_tc,
                         cudaFuncAttributeMaxDynamicSharedMemorySize, ATTN_SMEM);

    // Pre-pass: rna-tf32 rounding copies
    round_x<<<(Bb * Tt * Cc / 4) / 256, 256>>>(x);
    round_wq<<<(Cc * 3 * Cc / 4) / 256, 256>>>(w_qkv);
    round_wp<<<(Cc * Cc / 4) / 256, 256>>>(w_proj);

    // QKV GEMM: g_y(rounded x) x g_wq -> scatter rounded q/k/v
    gemm_tc<3 * Cc, true><<<dim3(24, 64), 256, GEMM_SMEM>>>(b_qkv, nullptr);
    // Flash attention (2 CTAs/SM): q/k/v -> g_y (rounded)
    attn_tc<<<dim3(Tt / 128, Bb * Hh), 256, ATTN_SMEM>>>();
    // Proj GEMM: g_y x g_wp + bias -> out (fp32)
    gemm_tc<Cc, false><<<dim3(8, 64), 256, GEMM_SMEM>>>(b_proj, out);
}